// round 12
// baseline (speedup 1.0000x reference)
#include <cuda_runtime.h>
#include <cuda_fp16.h>
#include <cstdint>

#define D 256
#define NNODES 32768
#define NREL 10
#define NBASES 4
#define NEDGES 524288
#define KTOT 1280          // 1024 (basis-agg part) + 256 (root part)

// ---------------- scratch (static device allocations; no cudaMalloc) ----------------
__device__ __half  g_Sh[(size_t)NNODES * 1024];  // 64 MB: aggregated basis sums (fp16)
__device__ __half  g_h1h[(size_t)NNODES * D];    // 16 MB: hidden activations (fp16)
__device__ __half  g_xh[(size_t)NNODES * D];     // 16 MB: fp16 input x
__device__ __half  g_W0T[D * KTOT];              // W^T layer0: [n=256][k=1280] (fp16)
__device__ __half  g_W1T[D * KTOT];              // W^T layer1
__device__ float   g_bias[2][D];
__device__ int     g_cnt[NREL * NNODES];
__device__ int     g_rowptr[NNODES + 1];
__device__ int     g_cursor[NNODES];
__device__ int     g_csr_src[NEDGES];
__device__ float4  g_ew0[NEDGES];
__device__ float4  g_ew1[NEDGES];

// ---------------- helpers ----------------
__device__ __forceinline__ void cp_async16(uint32_t saddr, const void* gaddr) {
    asm volatile("cp.async.cg.shared.global [%0], [%1], 16;\n" :: "r"(saddr), "l"(gaddr));
}

__device__ __forceinline__ void mma_fp16(float* d, const uint32_t* a, const uint32_t* b) {
    asm volatile(
        "mma.sync.aligned.m16n8k16.row.col.f32.f16.f16.f32 "
        "{%0,%1,%2,%3}, {%4,%5,%6,%7}, {%8,%9}, {%0,%1,%2,%3};\n"
        : "+f"(d[0]), "+f"(d[1]), "+f"(d[2]), "+f"(d[3])
        : "r"(a[0]), "r"(a[1]), "r"(a[2]), "r"(a[3]), "r"(b[0]), "r"(b[1]));
}

__device__ __forceinline__ void ldsm_x4(uint32_t& r0, uint32_t& r1, uint32_t& r2,
                                        uint32_t& r3, uint32_t saddr) {
    asm volatile("ldmatrix.sync.aligned.m8n8.x4.shared.b16 {%0,%1,%2,%3}, [%4];"
                 : "=r"(r0), "=r"(r1), "=r"(r2), "=r"(r3) : "r"(saddr));
}

__device__ __forceinline__ void ffma2(uint64_t& acc, uint64_t a, uint64_t b) {
    asm("fma.rn.f32x2 %0, %1, %2, %0;" : "+l"(acc) : "l"(a), "l"(b));
}

__device__ __forceinline__ uint64_t packf2(float lo, float hi) {
    uint64_t v;
    asm("mov.b64 %0, {%1, %2};" : "=l"(v) : "f"(lo), "f"(hi));
    return v;
}

__device__ __forceinline__ float2 unpackf2(uint64_t v) {
    float2 o;
    asm("mov.b64 {%0, %1}, %2;" : "=f"(o.x), "=f"(o.y) : "l"(v));
    return o;
}

__device__ __forceinline__ uint2 pack4h(float x, float y, float z, float w) {
    __half2 p0 = __floats2half2_rn(x, y);
    __half2 p1 = __floats2half2_rn(z, w);
    uint2 o;
    o.x = *(uint32_t*)&p0;
    o.y = *(uint32_t*)&p1;
    return o;
}

// ---------------- zero the (rel,dst) histogram ----------------
__global__ void zero_counts_kernel() {
    int i = blockIdx.x * blockDim.x + threadIdx.x;
    if (i < NREL * NNODES) g_cnt[i] = 0;
}

// ---------------- histogram (one atomic per edge) ----------------
__global__ void hist_kernel(const int* __restrict__ dst, const int* __restrict__ rel) {
    int e = blockIdx.x * blockDim.x + threadIdx.x;
    if (e >= NEDGES) return;
    atomicAdd(&g_cnt[rel[e] * NNODES + dst[e]], 1);
}

// ---------------- degrees (from cnt) + exclusive scan (single block) ----------------
__global__ void scan_kernel() {
    __shared__ int sums[1024];
    const int t = threadIdx.x;
    const int base = t * 32;
    int local[32];
    int s = 0;
#pragma unroll
    for (int i = 0; i < 32; ++i) {
        int deg = 0;
#pragma unroll
        for (int r = 0; r < NREL; ++r) deg += g_cnt[r * NNODES + base + i];
        local[i] = s;
        s += deg;
    }
    sums[t] = s;
    __syncthreads();
    for (int off = 1; off < 1024; off <<= 1) {
        int v = 0;
        if (t >= off) v = sums[t - off];
        __syncthreads();
        if (t >= off) sums[t] += v;
        __syncthreads();
    }
    const int chunk_off = (t == 0) ? 0 : sums[t - 1];
#pragma unroll
    for (int i = 0; i < 32; ++i) {
        int v = chunk_off + local[i];
        g_rowptr[base + i] = v;
        g_cursor[base + i] = v;
    }
    if (t == 1023) g_rowptr[NNODES] = sums[1023];
}

// ---------------- scatter: CSR order src + precomputed per-edge weights -----------
__global__ void scatter_kernel(const int* __restrict__ src, const int* __restrict__ dst,
                               const int* __restrict__ rel,
                               const float* __restrict__ comp0,
                               const float* __restrict__ comp1) {
    int e = blockIdx.x * blockDim.x + threadIdx.x;
    if (e >= NEDGES) return;
    int d = dst[e];
    int r = rel[e];
    int p = atomicAdd(&g_cursor[d], 1);
    float inv = 1.0f / (float)g_cnt[r * NNODES + d];
    g_csr_src[p] = src[e];
    g_ew0[p] = make_float4(comp0[r * 4 + 0] * inv, comp0[r * 4 + 1] * inv,
                           comp0[r * 4 + 2] * inv, comp0[r * 4 + 3] * inv);
    g_ew1[p] = make_float4(comp1[r * 4 + 0] * inv, comp1[r * 4 + 1] * inv,
                           comp1[r * 4 + 2] * inv, comp1[r * 4 + 3] * inv);
}

// ---------------- fused operand prep: x->fp16, W^T (both layers), bias -------------
__global__ void prep_kernel(const float* __restrict__ x,
                            const float* __restrict__ basis0, const float* __restrict__ root0,
                            const float* __restrict__ basis1, const float* __restrict__ root1,
                            const float* __restrict__ bias0, const float* __restrict__ bias1) {
    int i = blockIdx.x * blockDim.x + threadIdx.x;
    if (i < NNODES * D) g_xh[i] = __float2half_rn(x[i]);
    if (i < D * KTOT) {
        int n = i / KTOT;
        int k = i % KTOT;
        float v0, v1;
        if (k < NBASES * D) {
            int b = k >> 8;
            int r = k & 255;
            v0 = basis0[((size_t)b * D + r) * D + n];
            v1 = basis1[((size_t)b * D + r) * D + n];
        } else {
            v0 = root0[(size_t)(k - NBASES * D) * D + n];
            v1 = root1[(size_t)(k - NBASES * D) * D + n];
        }
        g_W0T[i] = __float2half_rn(v0);
        g_W1T[i] = __float2half_rn(v1);
    }
    if (i < D) { g_bias[0][i] = bias0[i]; g_bias[1][i] = bias1[i]; }
}

// ---------------- aggregation: S[dst, b, :] = sum_e w_b(e) feat[src] ----------------
// 512 threads per block = 8 dst nodes; packed f32x2 FFMA2 accumulation (exact).
__global__ __launch_bounds__(512) void aggregate_kernel(int layer) {
    const uint2* __restrict__ featv = (const uint2*)(layer ? g_h1h : g_xh);
    const float4* __restrict__ ew   = layer ? g_ew1 : g_ew0;
    const int dst = blockIdx.x * 8 + (threadIdx.x >> 6);
    const int t = threadIdx.x & 63;   // each owns 4 columns

    uint64_t acc[4][2] = {};          // 4 bases x (c01, c23) packed f32x2
    const int beg = g_rowptr[dst];
    const int end = g_rowptr[dst + 1];
    int e = beg;

    auto accum = [&](const float4& wt, const uint2& u) {
        float2 f01 = __half22float2(*(const __half2*)&u.x);
        float2 f23 = __half22float2(*(const __half2*)&u.y);
        uint64_t v01 = packf2(f01.x, f01.y);
        uint64_t v23 = packf2(f23.x, f23.y);
        uint64_t w0 = packf2(wt.x, wt.x);
        uint64_t w1 = packf2(wt.y, wt.y);
        uint64_t w2 = packf2(wt.z, wt.z);
        uint64_t w3 = packf2(wt.w, wt.w);
        ffma2(acc[0][0], w0, v01); ffma2(acc[0][1], w0, v23);
        ffma2(acc[1][0], w1, v01); ffma2(acc[1][1], w1, v23);
        ffma2(acc[2][0], w2, v01); ffma2(acc[2][1], w2, v23);
        ffma2(acc[3][0], w3, v01); ffma2(acc[3][1], w3, v23);
    };

    for (; e + 4 <= end; e += 4) {
        const int s0 = __ldg(&g_csr_src[e + 0]);
        const int s1 = __ldg(&g_csr_src[e + 1]);
        const int s2 = __ldg(&g_csr_src[e + 2]);
        const int s3 = __ldg(&g_csr_src[e + 3]);
        const uint2 u0 = __ldg(&featv[(size_t)s0 * 64 + t]);
        const uint2 u1 = __ldg(&featv[(size_t)s1 * 64 + t]);
        const uint2 u2 = __ldg(&featv[(size_t)s2 * 64 + t]);
        const uint2 u3 = __ldg(&featv[(size_t)s3 * 64 + t]);
        const float4 w0 = __ldg(&ew[e + 0]);
        const float4 w1 = __ldg(&ew[e + 1]);
        const float4 w2 = __ldg(&ew[e + 2]);
        const float4 w3 = __ldg(&ew[e + 3]);
        accum(w0, u0);
        accum(w1, u1);
        accum(w2, u2);
        accum(w3, u3);
    }
    for (; e < end; ++e) {
        const int s = __ldg(&g_csr_src[e]);
        const float4 wt = __ldg(&ew[e]);
        const uint2 u = __ldg(&featv[(size_t)s * 64 + t]);
        accum(wt, u);
    }

    uint2* Sp = (uint2*)(g_Sh + (size_t)dst * 1024);
#pragma unroll
    for (int b = 0; b < 4; ++b) {
        float2 c01 = unpackf2(acc[b][0]);
        float2 c23 = unpackf2(acc[b][1]);
        Sp[b * 64 + t] = pack4h(c01.x, c01.y, c23.x, c23.y);
    }
}

// ---------------- fp16 tensor-core GEMM (mma.sync.m16n8k16 + ldmatrix) ------------
// C[32768,256] = A[32768,1280] @ W[1280,256] (+bias, opt relu)
// One CTA per 128 M-rows covers ALL N=256: 512 threads (16 warps, 2M x 8N),
// warp tile 64x32. A read ONCE per layer. 4-stage cp.async, LDSM fragments.
#define PITCH 40                               // halfs per smem row (32 + 8 pad)
#define STAGE_HALFS ((128 + 256) * PITCH)      // A[128][40] + B[256][40]
#define NSTAGE 4
#define NIT (KTOT / 32)                        // 40
#define GEMM_SMEM (NSTAGE * STAGE_HALFS * 2)   // 122880 bytes

__global__ __launch_bounds__(512, 1) void gemm_fp16_kernel(float* __restrict__ out_ext, int layer) {
    extern __shared__ __half smem[];

    const __half* __restrict__ Sg = g_Sh;
    const __half* __restrict__ Rg = layer ? g_h1h : g_xh;
    const __half* __restrict__ WT = layer ? g_W1T : g_W0T;

    const int tid  = threadIdx.x;
    const int warp = tid >> 5, lane = tid & 31;
    const int g  = lane >> 2, t4 = lane & 3;
    const int wm = warp >> 3, wn = warp & 7;   // 2 x 8
    const int by = blockIdx.x * 128;

    const uint32_t smem_base = (uint32_t)__cvta_generic_to_shared(smem);

    // ldmatrix per-lane byte offsets within a stage:
    const uint32_t a_lane = (uint32_t)(((wm * 64 + (lane & 7) + ((lane >> 3) & 1) * 8) * PITCH
                                        + (lane >> 4) * 8) * 2);
    const uint32_t b_lane = (uint32_t)(((wn * 32 + (lane >> 4) * 8 + (lane & 7)) * PITCH
                                        + ((lane >> 3) & 1) * 8) * 2);

    // gmem->smem: 16B units. A: 512 units (1/thread). B: 1024 units (2/thread).
    const int r16 = tid >> 2;             // 0..127
    const int c16 = tid & 3;              // chunk 0..3

    float acc[4][4][4];
#pragma unroll
    for (int i = 0; i < 4; ++i)
#pragma unroll
        for (int j = 0; j < 4; ++j)
#pragma unroll
            for (int q = 0; q < 4; ++q) acc[i][j][q] = 0.f;

    auto issue = [&](int it) {
        const int k0 = it * 32;
        const int buf = it % NSTAGE;
        const __half* Ab;
        int astr;
        if (k0 < 1024) { Ab = Sg + (size_t)by * 1024 + k0; astr = 1024; }
        else           { Ab = Rg + (size_t)by * 256 + (k0 - 1024); astr = 256; }
        const uint32_t dA = smem_base + buf * STAGE_HALFS * 2;
        const uint32_t dB = dA + 128 * PITCH * 2;
        cp_async16(dA + (r16 * PITCH + c16 * 8) * 2, Ab + (size_t)r16 * astr + c16 * 8);
#pragma unroll
        for (int p = 0; p < 2; ++p) {
            int n = r16 + p * 128;
            cp_async16(dB + (n * PITCH + c16 * 8) * 2,
                       WT + (size_t)n * KTOT + k0 + c16 * 8);
        }
        asm volatile("cp.async.commit_group;\n" ::);
    };

    issue(0);
    issue(1);
    issue(2);

    for (int it = 0; it < NIT; ++it) {
        if (it >= NIT - 3) asm volatile("cp.async.wait_group 0;\n" ::);
        else               asm volatile("cp.async.wait_group 2;\n" ::);
        __syncthreads();
        if (it + 3 < NIT) issue(it + 3);

        const int buf = it % NSTAGE;
        const uint32_t cA = smem_base + buf * STAGE_HALFS * 2 + a_lane;
        const uint32_t cB = smem_base + buf * STAGE_HALFS * 2 + 128 * PITCH * 2 + b_lane;

#pragma unroll
        for (int kk = 0; kk < 32; kk += 16) {
            uint32_t af[4][4], bf[4][2];
#pragma unroll
            for (int mi = 0; mi < 4; ++mi)
                ldsm_x4(af[mi][0], af[mi][1], af[mi][2], af[mi][3],
                        cA + (mi * 16 * PITCH + kk) * 2);
#pragma unroll
            for (int nb = 0; nb < 2; ++nb)
                ldsm_x4(bf[2 * nb][0], bf[2 * nb][1], bf[2 * nb + 1][0], bf[2 * nb + 1][1],
                        cB + (nb * 16 * PITCH + kk) * 2);
#pragma unroll
            for (int mi = 0; mi < 4; ++mi)
#pragma unroll
                for (int ni = 0; ni < 4; ++ni)
                    mma_fp16(acc[mi][ni], af[mi], bf[ni]);
        }
    }

    // epilogue
#pragma unroll
    for (int mi = 0; mi < 4; ++mi) {
        const int row = by + wm * 64 + mi * 16 + g;
#pragma unroll
        for (int ni = 0; ni < 4; ++ni) {
            const int col = wn * 32 + ni * 8 + t4 * 2;
            const float b0 = g_bias[layer][col];
            const float b1 = g_bias[layer][col + 1];
            float v0 = acc[mi][ni][0] + b0, v1 = acc[mi][ni][1] + b1;
            float v2 = acc[mi][ni][2] + b0, v3 = acc[mi][ni][3] + b1;
            if (layer == 0) {
                v0 = fmaxf(v0, 0.f); v1 = fmaxf(v1, 0.f);
                v2 = fmaxf(v2, 0.f); v3 = fmaxf(v3, 0.f);
                *(__half2*)(g_h1h + (size_t)row * 256 + col)       = __floats2half2_rn(v0, v1);
                *(__half2*)(g_h1h + (size_t)(row + 8) * 256 + col) = __floats2half2_rn(v2, v3);
            } else {
                *(float2*)(out_ext + (size_t)row * 256 + col)       = make_float2(v0, v1);
                *(float2*)(out_ext + (size_t)(row + 8) * 256 + col) = make_float2(v2, v3);
            }
        }
    }
}

// ---------------- launch ----------------
extern "C" void kernel_launch(void* const* d_in, const int* in_sizes, int n_in,
                              void* d_out, int out_size) {
    const float* x      = (const float*)d_in[0];
    const int*   edges  = (const int*)d_in[3];
    const int*   rel    = (const int*)d_in[4];
    const float* basis0 = (const float*)d_in[5];
    const float* comp0  = (const float*)d_in[6];
    const float* root0  = (const float*)d_in[7];
    const float* bias0  = (const float*)d_in[8];
    const float* basis1 = (const float*)d_in[9];
    const float* comp1  = (const float*)d_in[10];
    const float* root1  = (const float*)d_in[11];
    const float* bias1  = (const float*)d_in[12];
    float* out = (float*)d_out;

    const int* src = edges;
    const int* dst = edges + NEDGES;

    cudaFuncSetAttribute(gemm_fp16_kernel,
                         cudaFuncAttributeMaxDynamicSharedMemorySize, GEMM_SMEM);

    // CSR + per-edge weights (shared by both layers)
    zero_counts_kernel<<<(NREL * NNODES + 255) / 256, 256>>>();
    hist_kernel<<<(NEDGES + 255) / 256, 256>>>(dst, rel);
    scan_kernel<<<1, 1024>>>();
    scatter_kernel<<<(NEDGES + 255) / 256, 256>>>(src, dst, rel, comp0, comp1);

    // fused fp16 operand prep
    prep_kernel<<<(NNODES * D + 255) / 256, 256>>>(x, basis0, root0, basis1, root1,
                                                   bias0, bias1);

    // Layer 0: aggregate(x) -> S; [S|x] @ W0 + bias0, ReLU -> h1
    aggregate_kernel<<<NNODES / 8, 512>>>(0);
    gemm_fp16_kernel<<<NNODES / 128, 512, GEMM_SMEM>>>(nullptr, 0);

    // Layer 1: aggregate(h1) -> S; [S|h1] @ W1 + bias1 -> out
    aggregate_kernel<<<NNODES / 8, 512>>>(1);
    gemm_fp16_kernel<<<NNODES / 128, 512, GEMM_SMEM>>>(out, 1);
}

// round 13
// speedup vs baseline: 1.4758x; 1.4758x over previous
#include <cuda_runtime.h>
#include <cuda_fp16.h>
#include <cstdint>

#define D 256
#define NNODES 32768
#define NREL 10
#define NBASES 4
#define NEDGES 524288
#define KTOT 1280          // 1024 (basis-agg part) + 256 (root part)

// ---------------- scratch (static device allocations; no cudaMalloc) ----------------
__device__ __half  g_Sh[(size_t)NNODES * 1024];  // 64 MB: aggregated basis sums (fp16)
__device__ __half  g_h1h[(size_t)NNODES * D];    // 16 MB: hidden activations (fp16)
__device__ __half  g_xh[(size_t)NNODES * D];     // 16 MB: fp16 input x
__device__ __half  g_W0T[D * KTOT];              // W^T layer0: [n=256][k=1280] (fp16)
__device__ __half  g_W1T[D * KTOT];              // W^T layer1
__device__ float   g_bias[2][D];
__device__ int     g_cnt[NREL * NNODES];
__device__ int     g_rowptr[NNODES + 1];
__device__ int     g_cursor[NNODES];
__device__ int     g_part[32];
__device__ int     g_poff[32];
__device__ uint2   g_ep[NEDGES];                 // per-edge: {src | rel<<16, f32 inv}
__device__ int     g_csr_src[NEDGES];
__device__ float4  g_ew0[NEDGES];
__device__ float4  g_ew1[NEDGES];

// ---------------- helpers ----------------
__device__ __forceinline__ void cp_async16(uint32_t saddr, const void* gaddr) {
    asm volatile("cp.async.cg.shared.global [%0], [%1], 16;\n" :: "r"(saddr), "l"(gaddr));
}

__device__ __forceinline__ void mma_fp16(float* d, const uint32_t* a, const uint32_t* b) {
    asm volatile(
        "mma.sync.aligned.m16n8k16.row.col.f32.f16.f16.f32 "
        "{%0,%1,%2,%3}, {%4,%5,%6,%7}, {%8,%9}, {%0,%1,%2,%3};\n"
        : "+f"(d[0]), "+f"(d[1]), "+f"(d[2]), "+f"(d[3])
        : "r"(a[0]), "r"(a[1]), "r"(a[2]), "r"(a[3]), "r"(b[0]), "r"(b[1]));
}

__device__ __forceinline__ void ldsm_x4(uint32_t& r0, uint32_t& r1, uint32_t& r2,
                                        uint32_t& r3, uint32_t saddr) {
    asm volatile("ldmatrix.sync.aligned.m8n8.x4.shared.b16 {%0,%1,%2,%3}, [%4];"
                 : "=r"(r0), "=r"(r1), "=r"(r2), "=r"(r3) : "r"(saddr));
}

__device__ __forceinline__ void ffma2(uint64_t& acc, uint64_t a, uint64_t b) {
    asm("fma.rn.f32x2 %0, %1, %2, %0;" : "+l"(acc) : "l"(a), "l"(b));
}

__device__ __forceinline__ uint64_t packf2(float lo, float hi) {
    uint64_t v;
    asm("mov.b64 %0, {%1, %2};" : "=l"(v) : "f"(lo), "f"(hi));
    return v;
}

__device__ __forceinline__ float2 unpackf2(uint64_t v) {
    float2 o;
    asm("mov.b64 {%0, %1}, %2;" : "=f"(o.x), "=f"(o.y) : "l"(v));
    return o;
}

__device__ __forceinline__ uint2 pack4h(float x, float y, float z, float w) {
    __half2 p0 = __floats2half2_rn(x, y);
    __half2 p1 = __floats2half2_rn(z, w);
    uint2 o;
    o.x = *(uint32_t*)&p0;
    o.y = *(uint32_t*)&p1;
    return o;
}

// ---------------- zero the (rel,dst) histogram ----------------
__global__ void zero_counts_kernel() {
    int i = blockIdx.x * blockDim.x + threadIdx.x;
    if (i < NREL * NNODES) g_cnt[i] = 0;
}

// ---------------- histogram (one atomic per edge) ----------------
__global__ void hist_kernel(const int* __restrict__ dst, const int* __restrict__ rel) {
    int e = blockIdx.x * blockDim.x + threadIdx.x;
    if (e >= NEDGES) return;
    atomicAdd(&g_cnt[rel[e] * NNODES + dst[e]], 1);
}

// ---------------- parallel scan, phase 1: per-block exclusive scan of degrees ------
__global__ __launch_bounds__(1024) void scan1_kernel() {
    __shared__ int s[1024];
    const int t = threadIdx.x;
    const int i = blockIdx.x * 1024 + t;
    int deg = 0;
#pragma unroll
    for (int r = 0; r < NREL; ++r) deg += g_cnt[r * NNODES + i];
    s[t] = deg;
    __syncthreads();
    for (int off = 1; off < 1024; off <<= 1) {
        int v = 0;
        if (t >= off) v = s[t - off];
        __syncthreads();
        if (t >= off) s[t] += v;
        __syncthreads();
    }
    g_rowptr[i] = (t == 0) ? 0 : s[t - 1];      // block-local exclusive
    if (t == 1023) g_part[blockIdx.x] = s[1023];
}

// ---------------- phase 2: scan the 32 block totals (single warp) ------------------
__global__ void scan2_kernel() {
    const int t = threadIdx.x;  // 32 threads
    int v = g_part[t];
    int orig = v;
#pragma unroll
    for (int off = 1; off < 32; off <<= 1) {
        int n = __shfl_up_sync(0xFFFFFFFF, v, off);
        if (t >= off) v += n;
    }
    g_poff[t] = v - orig;                        // exclusive offset
    if (t == 31) g_rowptr[NNODES] = v;           // grand total
}

// ---------------- phase 3: add block offsets ---------------------------------------
__global__ __launch_bounds__(1024) void scan3_kernel() {
    const int i = blockIdx.x * 1024 + threadIdx.x;
    int v = g_rowptr[i] + g_poff[blockIdx.x];
    g_rowptr[i] = v;
    g_cursor[i] = v;
}

// ---------------- scatter: packed (src,rel,inv) in CSR(dst) order (8B/edge) --------
__global__ void scatter_kernel(const int* __restrict__ src, const int* __restrict__ dst,
                               const int* __restrict__ rel) {
    int e = blockIdx.x * blockDim.x + threadIdx.x;
    if (e >= NEDGES) return;
    int d = dst[e];
    int r = rel[e];
    int p = atomicAdd(&g_cursor[d], 1);
    float inv = 1.0f / (float)g_cnt[r * NNODES + d];
    g_ep[p] = make_uint2((uint32_t)src[e] | ((uint32_t)r << 16), __float_as_uint(inv));
}

// ---------------- expand: coalesced materialization of src + per-edge weights ------
__global__ void expand_kernel(const float* __restrict__ comp0,
                              const float* __restrict__ comp1) {
    int e = blockIdx.x * blockDim.x + threadIdx.x;
    if (e >= NEDGES) return;
    uint2 ep = g_ep[e];
    int r = ep.x >> 16;
    float inv = __uint_as_float(ep.y);
    g_csr_src[e] = (int)(ep.x & 0xFFFF);
    g_ew0[e] = make_float4(comp0[r * 4 + 0] * inv, comp0[r * 4 + 1] * inv,
                           comp0[r * 4 + 2] * inv, comp0[r * 4 + 3] * inv);
    g_ew1[e] = make_float4(comp1[r * 4 + 0] * inv, comp1[r * 4 + 1] * inv,
                           comp1[r * 4 + 2] * inv, comp1[r * 4 + 3] * inv);
}

// ---------------- fused operand prep: x->fp16, W^T (both layers), bias -------------
__global__ void prep_kernel(const float* __restrict__ x,
                            const float* __restrict__ basis0, const float* __restrict__ root0,
                            const float* __restrict__ basis1, const float* __restrict__ root1,
                            const float* __restrict__ bias0, const float* __restrict__ bias1) {
    int i = blockIdx.x * blockDim.x + threadIdx.x;
    if (i < NNODES * D) g_xh[i] = __float2half_rn(x[i]);
    if (i < D * KTOT) {
        int n = i / KTOT;
        int k = i % KTOT;
        float v0, v1;
        if (k < NBASES * D) {
            int b = k >> 8;
            int r = k & 255;
            v0 = basis0[((size_t)b * D + r) * D + n];
            v1 = basis1[((size_t)b * D + r) * D + n];
        } else {
            v0 = root0[(size_t)(k - NBASES * D) * D + n];
            v1 = root1[(size_t)(k - NBASES * D) * D + n];
        }
        g_W0T[i] = __float2half_rn(v0);
        g_W1T[i] = __float2half_rn(v1);
    }
    if (i < D) { g_bias[0][i] = bias0[i]; g_bias[1][i] = bias1[i]; }
}

// ---------------- aggregation: S[dst, b, :] = sum_e w_b(e) feat[src] ----------------
// 512 threads per block = 8 dst nodes; packed f32x2 FFMA2 accumulation (exact).
__global__ __launch_bounds__(512) void aggregate_kernel(int layer) {
    const uint2* __restrict__ featv = (const uint2*)(layer ? g_h1h : g_xh);
    const float4* __restrict__ ew   = layer ? g_ew1 : g_ew0;
    const int dst = blockIdx.x * 8 + (threadIdx.x >> 6);
    const int t = threadIdx.x & 63;   // each owns 4 columns

    uint64_t acc[4][2] = {};          // 4 bases x (c01, c23) packed f32x2
    const int beg = g_rowptr[dst];
    const int end = g_rowptr[dst + 1];
    int e = beg;

    auto accum = [&](const float4& wt, const uint2& u) {
        float2 f01 = __half22float2(*(const __half2*)&u.x);
        float2 f23 = __half22float2(*(const __half2*)&u.y);
        uint64_t v01 = packf2(f01.x, f01.y);
        uint64_t v23 = packf2(f23.x, f23.y);
        uint64_t w0 = packf2(wt.x, wt.x);
        uint64_t w1 = packf2(wt.y, wt.y);
        uint64_t w2 = packf2(wt.z, wt.z);
        uint64_t w3 = packf2(wt.w, wt.w);
        ffma2(acc[0][0], w0, v01); ffma2(acc[0][1], w0, v23);
        ffma2(acc[1][0], w1, v01); ffma2(acc[1][1], w1, v23);
        ffma2(acc[2][0], w2, v01); ffma2(acc[2][1], w2, v23);
        ffma2(acc[3][0], w3, v01); ffma2(acc[3][1], w3, v23);
    };

    for (; e + 4 <= end; e += 4) {
        const int s0 = __ldg(&g_csr_src[e + 0]);
        const int s1 = __ldg(&g_csr_src[e + 1]);
        const int s2 = __ldg(&g_csr_src[e + 2]);
        const int s3 = __ldg(&g_csr_src[e + 3]);
        const uint2 u0 = __ldg(&featv[(size_t)s0 * 64 + t]);
        const uint2 u1 = __ldg(&featv[(size_t)s1 * 64 + t]);
        const uint2 u2 = __ldg(&featv[(size_t)s2 * 64 + t]);
        const uint2 u3 = __ldg(&featv[(size_t)s3 * 64 + t]);
        const float4 w0 = __ldg(&ew[e + 0]);
        const float4 w1 = __ldg(&ew[e + 1]);
        const float4 w2 = __ldg(&ew[e + 2]);
        const float4 w3 = __ldg(&ew[e + 3]);
        accum(w0, u0);
        accum(w1, u1);
        accum(w2, u2);
        accum(w3, u3);
    }
    for (; e < end; ++e) {
        const int s = __ldg(&g_csr_src[e]);
        const float4 wt = __ldg(&ew[e]);
        const uint2 u = __ldg(&featv[(size_t)s * 64 + t]);
        accum(wt, u);
    }

    uint2* Sp = (uint2*)(g_Sh + (size_t)dst * 1024);
#pragma unroll
    for (int b = 0; b < 4; ++b) {
        float2 c01 = unpackf2(acc[b][0]);
        float2 c23 = unpackf2(acc[b][1]);
        Sp[b * 64 + t] = pack4h(c01.x, c01.y, c23.x, c23.y);
    }
}

// ---------------- fp16 tensor-core GEMM (mma.sync.m16n8k16 + ldmatrix) ------------
// C[32768,256] = A[32768,1280] @ W[1280,256] (+bias, opt relu)
// One CTA per 128 M-rows covers ALL N=256: 512 threads (16 warps, 2M x 8N),
// warp tile 64x32. A read ONCE per layer. 3-stage cp.async, LDSM fragments.
#define PITCH 40                               // halfs per smem row (32 + 8 pad)
#define STAGE_HALFS ((128 + 256) * PITCH)      // A[128][40] + B[256][40]
#define NSTAGE 3
#define NIT (KTOT / 32)                        // 40
#define GEMM_SMEM (NSTAGE * STAGE_HALFS * 2)   // 92160 bytes

__global__ __launch_bounds__(512, 1) void gemm_fp16_kernel(float* __restrict__ out_ext, int layer) {
    extern __shared__ __half smem[];

    const __half* __restrict__ Sg = g_Sh;
    const __half* __restrict__ Rg = layer ? g_h1h : g_xh;
    const __half* __restrict__ WT = layer ? g_W1T : g_W0T;

    const int tid  = threadIdx.x;
    const int warp = tid >> 5, lane = tid & 31;
    const int g  = lane >> 2, t4 = lane & 3;
    const int wm = warp >> 3, wn = warp & 7;   // 2 x 8
    const int by = blockIdx.x * 128;

    const uint32_t smem_base = (uint32_t)__cvta_generic_to_shared(smem);

    // ldmatrix per-lane byte offsets within a stage:
    const uint32_t a_lane = (uint32_t)(((wm * 64 + (lane & 7) + ((lane >> 3) & 1) * 8) * PITCH
                                        + (lane >> 4) * 8) * 2);
    const uint32_t b_lane = (uint32_t)(((wn * 32 + (lane >> 4) * 8 + (lane & 7)) * PITCH
                                        + ((lane >> 3) & 1) * 8) * 2);

    // gmem->smem: 16B units. A: 512 units (1/thread). B: 1024 units (2/thread).
    const int r16 = tid >> 2;             // 0..127
    const int c16 = tid & 3;              // chunk 0..3

    float acc[4][4][4];
#pragma unroll
    for (int i = 0; i < 4; ++i)
#pragma unroll
        for (int j = 0; j < 4; ++j)
#pragma unroll
            for (int q = 0; q < 4; ++q) acc[i][j][q] = 0.f;

    auto issue = [&](int it) {
        const int k0 = it * 32;
        const int buf = it % NSTAGE;
        const __half* Ab;
        int astr;
        if (k0 < 1024) { Ab = Sg + (size_t)by * 1024 + k0; astr = 1024; }
        else           { Ab = Rg + (size_t)by * 256 + (k0 - 1024); astr = 256; }
        const uint32_t dA = smem_base + buf * STAGE_HALFS * 2;
        const uint32_t dB = dA + 128 * PITCH * 2;
        cp_async16(dA + (r16 * PITCH + c16 * 8) * 2, Ab + (size_t)r16 * astr + c16 * 8);
#pragma unroll
        for (int p = 0; p < 2; ++p) {
            int n = r16 + p * 128;
            cp_async16(dB + (n * PITCH + c16 * 8) * 2,
                       WT + (size_t)n * KTOT + k0 + c16 * 8);
        }
        asm volatile("cp.async.commit_group;\n" ::);
    };

    issue(0);
    issue(1);

    for (int it = 0; it < NIT; ++it) {
        if (it == NIT - 1) asm volatile("cp.async.wait_group 0;\n" ::);
        else               asm volatile("cp.async.wait_group 1;\n" ::);
        __syncthreads();
        if (it + 2 < NIT) issue(it + 2);

        const int buf = it % NSTAGE;
        const uint32_t cA = smem_base + buf * STAGE_HALFS * 2 + a_lane;
        const uint32_t cB = smem_base + buf * STAGE_HALFS * 2 + 128 * PITCH * 2 + b_lane;

#pragma unroll
        for (int kk = 0; kk < 32; kk += 16) {
            uint32_t af[4][4], bf[4][2];
#pragma unroll
            for (int mi = 0; mi < 4; ++mi)
                ldsm_x4(af[mi][0], af[mi][1], af[mi][2], af[mi][3],
                        cA + (mi * 16 * PITCH + kk) * 2);
#pragma unroll
            for (int nb = 0; nb < 2; ++nb)
                ldsm_x4(bf[2 * nb][0], bf[2 * nb][1], bf[2 * nb + 1][0], bf[2 * nb + 1][1],
                        cB + (nb * 16 * PITCH + kk) * 2);
#pragma unroll
            for (int mi = 0; mi < 4; ++mi)
#pragma unroll
                for (int ni = 0; ni < 4; ++ni)
                    mma_fp16(acc[mi][ni], af[mi], bf[ni]);
        }
    }

    // epilogue
#pragma unroll
    for (int mi = 0; mi < 4; ++mi) {
        const int row = by + wm * 64 + mi * 16 + g;
#pragma unroll
        for (int ni = 0; ni < 4; ++ni) {
            const int col = wn * 32 + ni * 8 + t4 * 2;
            const float b0 = g_bias[layer][col];
            const float b1 = g_bias[layer][col + 1];
            float v0 = acc[mi][ni][0] + b0, v1 = acc[mi][ni][1] + b1;
            float v2 = acc[mi][ni][2] + b0, v3 = acc[mi][ni][3] + b1;
            if (layer == 0) {
                v0 = fmaxf(v0, 0.f); v1 = fmaxf(v1, 0.f);
                v2 = fmaxf(v2, 0.f); v3 = fmaxf(v3, 0.f);
                *(__half2*)(g_h1h + (size_t)row * 256 + col)       = __floats2half2_rn(v0, v1);
                *(__half2*)(g_h1h + (size_t)(row + 8) * 256 + col) = __floats2half2_rn(v2, v3);
            } else {
                *(float2*)(out_ext + (size_t)row * 256 + col)       = make_float2(v0, v1);
                *(float2*)(out_ext + (size_t)(row + 8) * 256 + col) = make_float2(v2, v3);
            }
        }
    }
}

// ---------------- launch ----------------
extern "C" void kernel_launch(void* const* d_in, const int* in_sizes, int n_in,
                              void* d_out, int out_size) {
    const float* x      = (const float*)d_in[0];
    const int*   edges  = (const int*)d_in[3];
    const int*   rel    = (const int*)d_in[4];
    const float* basis0 = (const float*)d_in[5];
    const float* comp0  = (const float*)d_in[6];
    const float* root0  = (const float*)d_in[7];
    const float* bias0  = (const float*)d_in[8];
    const float* basis1 = (const float*)d_in[9];
    const float* comp1  = (const float*)d_in[10];
    const float* root1  = (const float*)d_in[11];
    const float* bias1  = (const float*)d_in[12];
    float* out = (float*)d_out;

    const int* src = edges;
    const int* dst = edges + NEDGES;

    cudaFuncSetAttribute(gemm_fp16_kernel,
                         cudaFuncAttributeMaxDynamicSharedMemorySize, GEMM_SMEM);

    // CSR + per-edge weights (shared by both layers)
    zero_counts_kernel<<<(NREL * NNODES + 255) / 256, 256>>>();
    hist_kernel<<<(NEDGES + 255) / 256, 256>>>(dst, rel);
    scan1_kernel<<<NNODES / 1024, 1024>>>();
    scan2_kernel<<<1, 32>>>();
    scan3_kernel<<<NNODES / 1024, 1024>>>();
    scatter_kernel<<<(NEDGES + 255) / 256, 256>>>(src, dst, rel);
    expand_kernel<<<(NEDGES + 255) / 256, 256>>>(comp0, comp1);

    // fused fp16 operand prep
    prep_kernel<<<(NNODES * D + 255) / 256, 256>>>(x, basis0, root0, basis1, root1,
                                                   bias0, bias1);

    // Layer 0: aggregate(x) -> S; [S|x] @ W0 + bias0, ReLU -> h1
    aggregate_kernel<<<NNODES / 8, 512>>>(0);
    gemm_fp16_kernel<<<NNODES / 128, 512, GEMM_SMEM>>>(nullptr, 0);

    // Layer 1: aggregate(h1) -> S; [S|h1] @ W1 + bias1 -> out
    aggregate_kernel<<<NNODES / 8, 512>>>(1);
    gemm_fp16_kernel<<<NNODES / 128, 512, GEMM_SMEM>>>(out, 1);
}

// round 14
// speedup vs baseline: 1.5340x; 1.0394x over previous
#include <cuda_runtime.h>
#include <cuda_fp16.h>
#include <cstdint>

#define D 256
#define NNODES 32768
#define NREL 10
#define NBASES 4
#define NEDGES 524288
#define KTOT 1280          // 1024 (basis-agg part) + 256 (root part)

// ---------------- scratch (static device allocations; no cudaMalloc) ----------------
__device__ __half  g_Sh[(size_t)NNODES * 1024];  // 64 MB: aggregated basis sums (fp16)
__device__ __half  g_h1h[(size_t)NNODES * D];    // 16 MB: hidden activations (fp16)
__device__ __half  g_xh[(size_t)NNODES * D];     // 16 MB: fp16 input x
__device__ __half  g_W0T[D * KTOT];              // W^T layer0: [n=256][k=1280] (fp16)
__device__ __half  g_W1T[D * KTOT];              // W^T layer1
__device__ float   g_bias[2][D];
__device__ int     g_cnt[NREL * NNODES];
__device__ int     g_rowptr[NNODES + 1];
__device__ int     g_cursor[NNODES];
__device__ int     g_part[32];
__device__ uint2   g_ep[NEDGES];                 // per-edge: {src | rel<<16, f32 inv}
__device__ int     g_csr_src[NEDGES];
__device__ float4  g_ew0[NEDGES];
__device__ float4  g_ew1[NEDGES];

// ---------------- helpers ----------------
__device__ __forceinline__ void cp_async16(uint32_t saddr, const void* gaddr) {
    asm volatile("cp.async.cg.shared.global [%0], [%1], 16;\n" :: "r"(saddr), "l"(gaddr));
}

__device__ __forceinline__ void mma_fp16(float* d, const uint32_t* a, const uint32_t* b) {
    asm volatile(
        "mma.sync.aligned.m16n8k16.row.col.f32.f16.f16.f32 "
        "{%0,%1,%2,%3}, {%4,%5,%6,%7}, {%8,%9}, {%0,%1,%2,%3};\n"
        : "+f"(d[0]), "+f"(d[1]), "+f"(d[2]), "+f"(d[3])
        : "r"(a[0]), "r"(a[1]), "r"(a[2]), "r"(a[3]), "r"(b[0]), "r"(b[1]));
}

__device__ __forceinline__ void ldsm_x4(uint32_t& r0, uint32_t& r1, uint32_t& r2,
                                        uint32_t& r3, uint32_t saddr) {
    asm volatile("ldmatrix.sync.aligned.m8n8.x4.shared.b16 {%0,%1,%2,%3}, [%4];"
                 : "=r"(r0), "=r"(r1), "=r"(r2), "=r"(r3) : "r"(saddr));
}

__device__ __forceinline__ void ffma2(uint64_t& acc, uint64_t a, uint64_t b) {
    asm("fma.rn.f32x2 %0, %1, %2, %0;" : "+l"(acc) : "l"(a), "l"(b));
}

__device__ __forceinline__ uint64_t packf2(float lo, float hi) {
    uint64_t v;
    asm("mov.b64 %0, {%1, %2};" : "=l"(v) : "f"(lo), "f"(hi));
    return v;
}

__device__ __forceinline__ float2 unpackf2(uint64_t v) {
    float2 o;
    asm("mov.b64 {%0, %1}, %2;" : "=f"(o.x), "=f"(o.y) : "l"(v));
    return o;
}

__device__ __forceinline__ uint2 pack4h(float x, float y, float z, float w) {
    __half2 p0 = __floats2half2_rn(x, y);
    __half2 p1 = __floats2half2_rn(z, w);
    uint2 o;
    o.x = *(uint32_t*)&p0;
    o.y = *(uint32_t*)&p1;
    return o;
}

// ---------------- histogram (one atomic per edge) ----------------
__global__ void hist_kernel(const int* __restrict__ dst, const int* __restrict__ rel) {
    int e = blockIdx.x * blockDim.x + threadIdx.x;
    if (e >= NEDGES) return;
    atomicAdd(&g_cnt[rel[e] * NNODES + dst[e]], 1);
}

// ---------------- parallel scan, phase 1: per-block exclusive scan of degrees ------
__global__ __launch_bounds__(1024) void scan1_kernel() {
    __shared__ int s[1024];
    const int t = threadIdx.x;
    const int i = blockIdx.x * 1024 + t;
    int deg = 0;
#pragma unroll
    for (int r = 0; r < NREL; ++r) deg += g_cnt[r * NNODES + i];
    s[t] = deg;
    __syncthreads();
    for (int off = 1; off < 1024; off <<= 1) {
        int v = 0;
        if (t >= off) v = s[t - off];
        __syncthreads();
        if (t >= off) s[t] += v;
        __syncthreads();
    }
    g_rowptr[i] = (t == 0) ? 0 : s[t - 1];      // block-local exclusive
    if (t == 1023) g_part[blockIdx.x] = s[1023];
}

// ---------------- phase 2: redundant warp-scan of partials + add offsets -----------
__global__ __launch_bounds__(1024) void scan3_kernel() {
    __shared__ int s_off;
    if (threadIdx.x < 32) {
        int v = g_part[threadIdx.x];
        int incl = v;
#pragma unroll
        for (int o = 1; o < 32; o <<= 1) {
            int n = __shfl_up_sync(0xFFFFFFFF, incl, o);
            if ((int)threadIdx.x >= o) incl += n;
        }
        if (threadIdx.x == 31 && blockIdx.x == 0) g_rowptr[NNODES] = incl;
        if ((int)threadIdx.x == (int)blockIdx.x) s_off = incl - v;   // exclusive offset
    }
    __syncthreads();
    const int i = blockIdx.x * 1024 + threadIdx.x;
    int v = g_rowptr[i] + s_off;
    g_rowptr[i] = v;
    g_cursor[i] = v;
}

// ---------------- scatter: packed (src,rel,inv) in CSR(dst) order (8B/edge) --------
__global__ void scatter_kernel(const int* __restrict__ src, const int* __restrict__ dst,
                               const int* __restrict__ rel) {
    int e = blockIdx.x * blockDim.x + threadIdx.x;
    if (e >= NEDGES) return;
    int d = dst[e];
    int r = rel[e];
    int p = atomicAdd(&g_cursor[d], 1);
    float inv = 1.0f / (float)g_cnt[r * NNODES + d];
    g_ep[p] = make_uint2((uint32_t)src[e] | ((uint32_t)r << 16), __float_as_uint(inv));
}

// ---------------- expand: coalesced materialization of src + per-edge weights ------
__global__ void expand_kernel(const float* __restrict__ comp0,
                              const float* __restrict__ comp1) {
    int e = blockIdx.x * blockDim.x + threadIdx.x;
    if (e >= NEDGES) return;
    uint2 ep = g_ep[e];
    int r = ep.x >> 16;
    float inv = __uint_as_float(ep.y);
    g_csr_src[e] = (int)(ep.x & 0xFFFF);
    g_ew0[e] = make_float4(comp0[r * 4 + 0] * inv, comp0[r * 4 + 1] * inv,
                           comp0[r * 4 + 2] * inv, comp0[r * 4 + 3] * inv);
    g_ew1[e] = make_float4(comp1[r * 4 + 0] * inv, comp1[r * 4 + 1] * inv,
                           comp1[r * 4 + 2] * inv, comp1[r * 4 + 3] * inv);
}

// ---------------- fused prep: zero cnt, x->fp16, W^T (both layers), bias -----------
// Launched FIRST (before hist), so the g_cnt zeroing is ordered correctly.
__global__ void prep_kernel(const float* __restrict__ x,
                            const float* __restrict__ basis0, const float* __restrict__ root0,
                            const float* __restrict__ basis1, const float* __restrict__ root1,
                            const float* __restrict__ bias0, const float* __restrict__ bias1) {
    int i = blockIdx.x * blockDim.x + threadIdx.x;
    if (i < NNODES * D) g_xh[i] = __float2half_rn(x[i]);
    if (i < NREL * NNODES) g_cnt[i] = 0;
    if (i < D * KTOT) {
        int n = i / KTOT;
        int k = i % KTOT;
        float v0, v1;
        if (k < NBASES * D) {
            int b = k >> 8;
            int r = k & 255;
            v0 = basis0[((size_t)b * D + r) * D + n];
            v1 = basis1[((size_t)b * D + r) * D + n];
        } else {
            v0 = root0[(size_t)(k - NBASES * D) * D + n];
            v1 = root1[(size_t)(k - NBASES * D) * D + n];
        }
        g_W0T[i] = __float2half_rn(v0);
        g_W1T[i] = __float2half_rn(v1);
    }
    if (i < D) { g_bias[0][i] = bias0[i]; g_bias[1][i] = bias1[i]; }
}

// ---------------- aggregation: S[dst, b, :] = sum_e w_b(e) feat[src] ----------------
// 512 threads per block = 8 dst nodes; packed f32x2 FFMA2 accumulation (exact).
__global__ __launch_bounds__(512) void aggregate_kernel(int layer) {
    const uint2* __restrict__ featv = (const uint2*)(layer ? g_h1h : g_xh);
    const float4* __restrict__ ew   = layer ? g_ew1 : g_ew0;
    const int dst = blockIdx.x * 8 + (threadIdx.x >> 6);
    const int t = threadIdx.x & 63;   // each owns 4 columns

    uint64_t acc[4][2] = {};          // 4 bases x (c01, c23) packed f32x2
    const int beg = g_rowptr[dst];
    const int end = g_rowptr[dst + 1];
    int e = beg;

    auto accum = [&](const float4& wt, const uint2& u) {
        float2 f01 = __half22float2(*(const __half2*)&u.x);
        float2 f23 = __half22float2(*(const __half2*)&u.y);
        uint64_t v01 = packf2(f01.x, f01.y);
        uint64_t v23 = packf2(f23.x, f23.y);
        uint64_t w0 = packf2(wt.x, wt.x);
        uint64_t w1 = packf2(wt.y, wt.y);
        uint64_t w2 = packf2(wt.z, wt.z);
        uint64_t w3 = packf2(wt.w, wt.w);
        ffma2(acc[0][0], w0, v01); ffma2(acc[0][1], w0, v23);
        ffma2(acc[1][0], w1, v01); ffma2(acc[1][1], w1, v23);
        ffma2(acc[2][0], w2, v01); ffma2(acc[2][1], w2, v23);
        ffma2(acc[3][0], w3, v01); ffma2(acc[3][1], w3, v23);
    };

    for (; e + 4 <= end; e += 4) {
        const int s0 = __ldg(&g_csr_src[e + 0]);
        const int s1 = __ldg(&g_csr_src[e + 1]);
        const int s2 = __ldg(&g_csr_src[e + 2]);
        const int s3 = __ldg(&g_csr_src[e + 3]);
        const uint2 u0 = __ldg(&featv[(size_t)s0 * 64 + t]);
        const uint2 u1 = __ldg(&featv[(size_t)s1 * 64 + t]);
        const uint2 u2 = __ldg(&featv[(size_t)s2 * 64 + t]);
        const uint2 u3 = __ldg(&featv[(size_t)s3 * 64 + t]);
        const float4 w0 = __ldg(&ew[e + 0]);
        const float4 w1 = __ldg(&ew[e + 1]);
        const float4 w2 = __ldg(&ew[e + 2]);
        const float4 w3 = __ldg(&ew[e + 3]);
        accum(w0, u0);
        accum(w1, u1);
        accum(w2, u2);
        accum(w3, u3);
    }
    for (; e < end; ++e) {
        const int s = __ldg(&g_csr_src[e]);
        const float4 wt = __ldg(&ew[e]);
        const uint2 u = __ldg(&featv[(size_t)s * 64 + t]);
        accum(wt, u);
    }

    uint2* Sp = (uint2*)(g_Sh + (size_t)dst * 1024);
#pragma unroll
    for (int b = 0; b < 4; ++b) {
        float2 c01 = unpackf2(acc[b][0]);
        float2 c23 = unpackf2(acc[b][1]);
        Sp[b * 64 + t] = pack4h(c01.x, c01.y, c23.x, c23.y);
    }
}

// ---------------- fp16 tensor-core GEMM (mma.sync.m16n8k16 + ldmatrix) ------------
// C[32768,256] = A[32768,1280] @ W[1280,256] (+bias, opt relu)
// M=64 rows per CTA, full N=256: 256 threads (8 warps, 1M x 8N), warp tile 64x32.
// 2 CTAs/SM co-resident. 3-stage cp.async, LDSM fragments.
#define PITCH 40                               // halfs per smem row (32 + 8 pad)
#define STAGE_HALFS ((64 + 256) * PITCH)       // A[64][40] + B[256][40] = 12800
#define NSTAGE 3
#define NIT (KTOT / 32)                        // 40
#define GEMM_SMEM (NSTAGE * STAGE_HALFS * 2)   // 76800 bytes

__global__ __launch_bounds__(256, 2) void gemm_fp16_kernel(float* __restrict__ out_ext, int layer) {
    extern __shared__ __half smem[];

    const __half* __restrict__ Sg = g_Sh;
    const __half* __restrict__ Rg = layer ? g_h1h : g_xh;
    const __half* __restrict__ WT = layer ? g_W1T : g_W0T;

    const int tid  = threadIdx.x;
    const int warp = tid >> 5, lane = tid & 31;
    const int g  = lane >> 2, t4 = lane & 3;
    const int wn = warp;                       // 8 warps across N
    const int by = blockIdx.x * 64;

    const uint32_t smem_base = (uint32_t)__cvta_generic_to_shared(smem);

    // ldmatrix per-lane byte offsets within a stage:
    const uint32_t a_lane = (uint32_t)((((lane & 7) + ((lane >> 3) & 1) * 8) * PITCH
                                        + (lane >> 4) * 8) * 2);
    const uint32_t b_lane = (uint32_t)(((wn * 32 + (lane >> 4) * 8 + (lane & 7)) * PITCH
                                        + ((lane >> 3) & 1) * 8) * 2);

    // gmem->smem: 16B units. A: 256 units (1/thread). B: 1024 units (4/thread).
    const int r16 = tid >> 2;             // 0..63
    const int c16 = tid & 3;              // chunk 0..3

    float acc[4][4][4];
#pragma unroll
    for (int i = 0; i < 4; ++i)
#pragma unroll
        for (int j = 0; j < 4; ++j)
#pragma unroll
            for (int q = 0; q < 4; ++q) acc[i][j][q] = 0.f;

    auto issue = [&](int it) {
        const int k0 = it * 32;
        const int buf = it % NSTAGE;
        const __half* Ab;
        int astr;
        if (k0 < 1024) { Ab = Sg + (size_t)by * 1024 + k0; astr = 1024; }
        else           { Ab = Rg + (size_t)by * 256 + (k0 - 1024); astr = 256; }
        const uint32_t dA = smem_base + buf * STAGE_HALFS * 2;
        const uint32_t dB = dA + 64 * PITCH * 2;
        cp_async16(dA + (r16 * PITCH + c16 * 8) * 2, Ab + (size_t)r16 * astr + c16 * 8);
#pragma unroll
        for (int p = 0; p < 4; ++p) {
            int n = r16 + p * 64;
            cp_async16(dB + (n * PITCH + c16 * 8) * 2,
                       WT + (size_t)n * KTOT + k0 + c16 * 8);
        }
        asm volatile("cp.async.commit_group;\n" ::);
    };

    issue(0);
    issue(1);

    for (int it = 0; it < NIT; ++it) {
        if (it == NIT - 1) asm volatile("cp.async.wait_group 0;\n" ::);
        else               asm volatile("cp.async.wait_group 1;\n" ::);
        __syncthreads();
        if (it + 2 < NIT) issue(it + 2);

        const int buf = it % NSTAGE;
        const uint32_t cA = smem_base + buf * STAGE_HALFS * 2 + a_lane;
        const uint32_t cB = smem_base + buf * STAGE_HALFS * 2 + 64 * PITCH * 2 + b_lane;

#pragma unroll
        for (int kk = 0; kk < 32; kk += 16) {
            uint32_t af[4][4], bf[4][2];
#pragma unroll
            for (int mi = 0; mi < 4; ++mi)
                ldsm_x4(af[mi][0], af[mi][1], af[mi][2], af[mi][3],
                        cA + (mi * 16 * PITCH + kk) * 2);
#pragma unroll
            for (int nb = 0; nb < 2; ++nb)
                ldsm_x4(bf[2 * nb][0], bf[2 * nb][1], bf[2 * nb + 1][0], bf[2 * nb + 1][1],
                        cB + (nb * 16 * PITCH + kk) * 2);
#pragma unroll
            for (int mi = 0; mi < 4; ++mi)
#pragma unroll
                for (int ni = 0; ni < 4; ++ni)
                    mma_fp16(acc[mi][ni], af[mi], bf[ni]);
        }
    }

    // epilogue
#pragma unroll
    for (int mi = 0; mi < 4; ++mi) {
        const int row = by + mi * 16 + g;
#pragma unroll
        for (int ni = 0; ni < 4; ++ni) {
            const int col = wn * 32 + ni * 8 + t4 * 2;
            const float b0 = g_bias[layer][col];
            const float b1 = g_bias[layer][col + 1];
            float v0 = acc[mi][ni][0] + b0, v1 = acc[mi][ni][1] + b1;
            float v2 = acc[mi][ni][2] + b0, v3 = acc[mi][ni][3] + b1;
            if (layer == 0) {
                v0 = fmaxf(v0, 0.f); v1 = fmaxf(v1, 0.f);
                v2 = fmaxf(v2, 0.f); v3 = fmaxf(v3, 0.f);
                *(__half2*)(g_h1h + (size_t)row * 256 + col)       = __floats2half2_rn(v0, v1);
                *(__half2*)(g_h1h + (size_t)(row + 8) * 256 + col) = __floats2half2_rn(v2, v3);
            } else {
                *(float2*)(out_ext + (size_t)row * 256 + col)       = make_float2(v0, v1);
                *(float2*)(out_ext + (size_t)(row + 8) * 256 + col) = make_float2(v2, v3);
            }
        }
    }
}

// ---------------- launch ----------------
extern "C" void kernel_launch(void* const* d_in, const int* in_sizes, int n_in,
                              void* d_out, int out_size) {
    const float* x      = (const float*)d_in[0];
    const int*   edges  = (const int*)d_in[3];
    const int*   rel    = (const int*)d_in[4];
    const float* basis0 = (const float*)d_in[5];
    const float* comp0  = (const float*)d_in[6];
    const float* root0  = (const float*)d_in[7];
    const float* bias0  = (const float*)d_in[8];
    const float* basis1 = (const float*)d_in[9];
    const float* comp1  = (const float*)d_in[10];
    const float* root1  = (const float*)d_in[11];
    const float* bias1  = (const float*)d_in[12];
    float* out = (float*)d_out;

    const int* src = edges;
    const int* dst = edges + NEDGES;

    cudaFuncSetAttribute(gemm_fp16_kernel,
                         cudaFuncAttributeMaxDynamicSharedMemorySize, GEMM_SMEM);

    // fused prep first (also zeroes g_cnt for hist)
    prep_kernel<<<(NNODES * D + 255) / 256, 256>>>(x, basis0, root0, basis1, root1,
                                                   bias0, bias1);

    // CSR + per-edge weights (shared by both layers)
    hist_kernel<<<(NEDGES + 255) / 256, 256>>>(dst, rel);
    scan1_kernel<<<NNODES / 1024, 1024>>>();
    scan3_kernel<<<NNODES / 1024, 1024>>>();
    scatter_kernel<<<(NEDGES + 255) / 256, 256>>>(src, dst, rel);
    expand_kernel<<<(NEDGES + 255) / 256, 256>>>(comp0, comp1);

    // Layer 0: aggregate(x) -> S; [S|x] @ W0 + bias0, ReLU -> h1
    aggregate_kernel<<<NNODES / 8, 512>>>(0);
    gemm_fp16_kernel<<<NNODES / 64, 256, GEMM_SMEM>>>(nullptr, 0);

    // Layer 1: aggregate(h1) -> S; [S|h1] @ W1 + bias1 -> out
    aggregate_kernel<<<NNODES / 8, 512>>>(1);
    gemm_fp16_kernel<<<NNODES / 64, 256, GEMM_SMEM>>>(out, 1);
}

// round 15
// speedup vs baseline: 1.5470x; 1.0085x over previous
#include <cuda_runtime.h>
#include <cuda_fp16.h>
#include <cstdint>

#define D 256
#define NNODES 32768
#define NREL 10
#define NBASES 4
#define NEDGES 524288
#define KTOT 1280          // 1024 (basis-agg part) + 256 (root part)

// ---------------- scratch (static device allocations; no cudaMalloc) ----------------
__device__ __half  g_Sh[(size_t)NNODES * 1024];  // 64 MB: aggregated basis sums (fp16)
__device__ __half  g_h1h[(size_t)NNODES * D];    // 16 MB: hidden activations (fp16)
__device__ __half  g_xh[(size_t)NNODES * D];     // 16 MB: fp16 input x
__device__ __half  g_W0T[D * KTOT];              // W^T layer0: [n=256][k=1280] (fp16)
__device__ __half  g_W1T[D * KTOT];              // W^T layer1
__device__ float   g_bias[2][D];
__device__ int     g_cnt[NREL * NNODES];
__device__ int     g_rowptr[NNODES + 1];
__device__ int     g_cursor[NNODES];
__device__ int     g_part[32];
__device__ uint2   g_ep[NEDGES];                 // per-edge: {src | rel<<16, f32 inv}
__device__ int     g_csr_src[NEDGES];
__device__ float4  g_ew0[NEDGES];
__device__ float4  g_ew1[NEDGES];

// ---------------- helpers ----------------
__device__ __forceinline__ void cp_async16(uint32_t saddr, const void* gaddr) {
    asm volatile("cp.async.cg.shared.global [%0], [%1], 16;\n" :: "r"(saddr), "l"(gaddr));
}

__device__ __forceinline__ void mma_fp16(float* d, const uint32_t* a, const uint32_t* b) {
    asm volatile(
        "mma.sync.aligned.m16n8k16.row.col.f32.f16.f16.f32 "
        "{%0,%1,%2,%3}, {%4,%5,%6,%7}, {%8,%9}, {%0,%1,%2,%3};\n"
        : "+f"(d[0]), "+f"(d[1]), "+f"(d[2]), "+f"(d[3])
        : "r"(a[0]), "r"(a[1]), "r"(a[2]), "r"(a[3]), "r"(b[0]), "r"(b[1]));
}

__device__ __forceinline__ void ldsm_x4(uint32_t& r0, uint32_t& r1, uint32_t& r2,
                                        uint32_t& r3, uint32_t saddr) {
    asm volatile("ldmatrix.sync.aligned.m8n8.x4.shared.b16 {%0,%1,%2,%3}, [%4];"
                 : "=r"(r0), "=r"(r1), "=r"(r2), "=r"(r3) : "r"(saddr));
}

__device__ __forceinline__ void ffma2(uint64_t& acc, uint64_t a, uint64_t b) {
    asm("fma.rn.f32x2 %0, %1, %2, %0;" : "+l"(acc) : "l"(a), "l"(b));
}

__device__ __forceinline__ uint64_t packf2(float lo, float hi) {
    uint64_t v;
    asm("mov.b64 %0, {%1, %2};" : "=l"(v) : "f"(lo), "f"(hi));
    return v;
}

__device__ __forceinline__ float2 unpackf2(uint64_t v) {
    float2 o;
    asm("mov.b64 {%0, %1}, %2;" : "=f"(o.x), "=f"(o.y) : "l"(v));
    return o;
}

__device__ __forceinline__ uint2 pack4h(float x, float y, float z, float w) {
    __half2 p0 = __floats2half2_rn(x, y);
    __half2 p1 = __floats2half2_rn(z, w);
    uint2 o;
    o.x = *(uint32_t*)&p0;
    o.y = *(uint32_t*)&p1;
    return o;
}

// ---------------- zero the (rel,dst) histogram ----------------
__global__ void zero_counts_kernel() {
    int i = blockIdx.x * blockDim.x + threadIdx.x;
    if (i < NREL * NNODES) g_cnt[i] = 0;
}

// ---------------- histogram (one atomic per edge) ----------------
__global__ void hist_kernel(const int* __restrict__ dst, const int* __restrict__ rel) {
    int e = blockIdx.x * blockDim.x + threadIdx.x;
    if (e >= NEDGES) return;
    atomicAdd(&g_cnt[rel[e] * NNODES + dst[e]], 1);
}

// ---------------- parallel scan, phase 1: per-block exclusive scan of degrees ------
__global__ __launch_bounds__(1024) void scan1_kernel() {
    __shared__ int s[1024];
    const int t = threadIdx.x;
    const int i = blockIdx.x * 1024 + t;
    int deg = 0;
#pragma unroll
    for (int r = 0; r < NREL; ++r) deg += g_cnt[r * NNODES + i];
    s[t] = deg;
    __syncthreads();
    for (int off = 1; off < 1024; off <<= 1) {
        int v = 0;
        if (t >= off) v = s[t - off];
        __syncthreads();
        if (t >= off) s[t] += v;
        __syncthreads();
    }
    g_rowptr[i] = (t == 0) ? 0 : s[t - 1];      // block-local exclusive
    if (t == 1023) g_part[blockIdx.x] = s[1023];
}

// ---------------- phase 2: redundant warp-scan of partials + add offsets -----------
__global__ __launch_bounds__(1024) void scan3_kernel() {
    __shared__ int s_off;
    if (threadIdx.x < 32) {
        int v = g_part[threadIdx.x];
        int incl = v;
#pragma unroll
        for (int o = 1; o < 32; o <<= 1) {
            int n = __shfl_up_sync(0xFFFFFFFF, incl, o);
            if ((int)threadIdx.x >= o) incl += n;
        }
        if (threadIdx.x == 31 && blockIdx.x == 0) g_rowptr[NNODES] = incl;
        if ((int)threadIdx.x == (int)blockIdx.x) s_off = incl - v;   // exclusive offset
    }
    __syncthreads();
    const int i = blockIdx.x * 1024 + threadIdx.x;
    int v = g_rowptr[i] + s_off;
    g_rowptr[i] = v;
    g_cursor[i] = v;
}

// ---------------- scatter: packed (src,rel,inv) in CSR(dst) order (8B/edge) --------
__global__ void scatter_kernel(const int* __restrict__ src, const int* __restrict__ dst,
                               const int* __restrict__ rel) {
    int e = blockIdx.x * blockDim.x + threadIdx.x;
    if (e >= NEDGES) return;
    int d = dst[e];
    int r = rel[e];
    int p = atomicAdd(&g_cursor[d], 1);
    float inv = 1.0f / (float)g_cnt[r * NNODES + d];
    g_ep[p] = make_uint2((uint32_t)src[e] | ((uint32_t)r << 16), __float_as_uint(inv));
}

// ---------------- expand: coalesced materialization of src + per-edge weights ------
__global__ void expand_kernel(const float* __restrict__ comp0,
                              const float* __restrict__ comp1) {
    int e = blockIdx.x * blockDim.x + threadIdx.x;
    if (e >= NEDGES) return;
    uint2 ep = g_ep[e];
    int r = ep.x >> 16;
    float inv = __uint_as_float(ep.y);
    g_csr_src[e] = (int)(ep.x & 0xFFFF);
    g_ew0[e] = make_float4(comp0[r * 4 + 0] * inv, comp0[r * 4 + 1] * inv,
                           comp0[r * 4 + 2] * inv, comp0[r * 4 + 3] * inv);
    g_ew1[e] = make_float4(comp1[r * 4 + 0] * inv, comp1[r * 4 + 1] * inv,
                           comp1[r * 4 + 2] * inv, comp1[r * 4 + 3] * inv);
}

// ---------------- fused prep: x->fp16, W^T (both layers), bias ---------------------
__global__ void prep_kernel(const float* __restrict__ x,
                            const float* __restrict__ basis0, const float* __restrict__ root0,
                            const float* __restrict__ basis1, const float* __restrict__ root1,
                            const float* __restrict__ bias0, const float* __restrict__ bias1) {
    int i = blockIdx.x * blockDim.x + threadIdx.x;
    if (i < NNODES * D) g_xh[i] = __float2half_rn(x[i]);
    if (i < D * KTOT) {
        int n = i / KTOT;
        int k = i % KTOT;
        float v0, v1;
        if (k < NBASES * D) {
            int b = k >> 8;
            int r = k & 255;
            v0 = basis0[((size_t)b * D + r) * D + n];
            v1 = basis1[((size_t)b * D + r) * D + n];
        } else {
            v0 = root0[(size_t)(k - NBASES * D) * D + n];
            v1 = root1[(size_t)(k - NBASES * D) * D + n];
        }
        g_W0T[i] = __float2half_rn(v0);
        g_W1T[i] = __float2half_rn(v1);
    }
    if (i < D) { g_bias[0][i] = bias0[i]; g_bias[1][i] = bias1[i]; }
}

// ---------------- aggregation: S[dst, b, :] = sum_e w_b(e) feat[src] ----------------
// 512 threads per block = 8 dst nodes; packed f32x2 FFMA2 accumulation (exact).
__global__ __launch_bounds__(512) void aggregate_kernel(int layer) {
    const uint2* __restrict__ featv = (const uint2*)(layer ? g_h1h : g_xh);
    const float4* __restrict__ ew   = layer ? g_ew1 : g_ew0;
    const int dst = blockIdx.x * 8 + (threadIdx.x >> 6);
    const int t = threadIdx.x & 63;   // each owns 4 columns

    uint64_t acc[4][2] = {};          // 4 bases x (c01, c23) packed f32x2
    const int beg = g_rowptr[dst];
    const int end = g_rowptr[dst + 1];
    int e = beg;

    auto accum = [&](const float4& wt, const uint2& u) {
        float2 f01 = __half22float2(*(const __half2*)&u.x);
        float2 f23 = __half22float2(*(const __half2*)&u.y);
        uint64_t v01 = packf2(f01.x, f01.y);
        uint64_t v23 = packf2(f23.x, f23.y);
        uint64_t w0 = packf2(wt.x, wt.x);
        uint64_t w1 = packf2(wt.y, wt.y);
        uint64_t w2 = packf2(wt.z, wt.z);
        uint64_t w3 = packf2(wt.w, wt.w);
        ffma2(acc[0][0], w0, v01); ffma2(acc[0][1], w0, v23);
        ffma2(acc[1][0], w1, v01); ffma2(acc[1][1], w1, v23);
        ffma2(acc[2][0], w2, v01); ffma2(acc[2][1], w2, v23);
        ffma2(acc[3][0], w3, v01); ffma2(acc[3][1], w3, v23);
    };

    for (; e + 4 <= end; e += 4) {
        const int s0 = __ldg(&g_csr_src[e + 0]);
        const int s1 = __ldg(&g_csr_src[e + 1]);
        const int s2 = __ldg(&g_csr_src[e + 2]);
        const int s3 = __ldg(&g_csr_src[e + 3]);
        const uint2 u0 = __ldg(&featv[(size_t)s0 * 64 + t]);
        const uint2 u1 = __ldg(&featv[(size_t)s1 * 64 + t]);
        const uint2 u2 = __ldg(&featv[(size_t)s2 * 64 + t]);
        const uint2 u3 = __ldg(&featv[(size_t)s3 * 64 + t]);
        const float4 w0 = __ldg(&ew[e + 0]);
        const float4 w1 = __ldg(&ew[e + 1]);
        const float4 w2 = __ldg(&ew[e + 2]);
        const float4 w3 = __ldg(&ew[e + 3]);
        accum(w0, u0);
        accum(w1, u1);
        accum(w2, u2);
        accum(w3, u3);
    }
    for (; e < end; ++e) {
        const int s = __ldg(&g_csr_src[e]);
        const float4 wt = __ldg(&ew[e]);
        const uint2 u = __ldg(&featv[(size_t)s * 64 + t]);
        accum(wt, u);
    }

    uint2* Sp = (uint2*)(g_Sh + (size_t)dst * 1024);
#pragma unroll
    for (int b = 0; b < 4; ++b) {
        float2 c01 = unpackf2(acc[b][0]);
        float2 c23 = unpackf2(acc[b][1]);
        Sp[b * 64 + t] = pack4h(c01.x, c01.y, c23.x, c23.y);
    }
}

// ---------------- fp16 tensor-core GEMM (mma.sync.m16n8k16 + ldmatrix) ------------
// C[32768,256] = A[32768,1280] @ W[1280,256] (+bias, opt relu)
// M=64 rows per CTA, full N=256: 256 threads (8 warps, 1M x 8N), warp tile 64x32.
// 2 CTAs/SM co-resident. 3-stage cp.async, LDSM fragments.
#define PITCH 40                               // halfs per smem row (32 + 8 pad)
#define STAGE_HALFS ((64 + 256) * PITCH)       // A[64][40] + B[256][40] = 12800
#define NSTAGE 3
#define NIT (KTOT / 32)                        // 40
#define GEMM_SMEM (NSTAGE * STAGE_HALFS * 2)   // 76800 bytes

__global__ __launch_bounds__(256, 2) void gemm_fp16_kernel(float* __restrict__ out_ext, int layer) {
    extern __shared__ __half smem[];

    const __half* __restrict__ Sg = g_Sh;
    const __half* __restrict__ Rg = layer ? g_h1h : g_xh;
    const __half* __restrict__ WT = layer ? g_W1T : g_W0T;

    const int tid  = threadIdx.x;
    const int warp = tid >> 5, lane = tid & 31;
    const int g  = lane >> 2, t4 = lane & 3;
    const int wn = warp;                       // 8 warps across N
    const int by = blockIdx.x * 64;

    const uint32_t smem_base = (uint32_t)__cvta_generic_to_shared(smem);

    // ldmatrix per-lane byte offsets within a stage:
    const uint32_t a_lane = (uint32_t)((((lane & 7) + ((lane >> 3) & 1) * 8) * PITCH
                                        + (lane >> 4) * 8) * 2);
    const uint32_t b_lane = (uint32_t)(((wn * 32 + (lane >> 4) * 8 + (lane & 7)) * PITCH
                                        + ((lane >> 3) & 1) * 8) * 2);

    // gmem->smem: 16B units. A: 256 units (1/thread). B: 1024 units (4/thread).
    const int r16 = tid >> 2;             // 0..63
    const int c16 = tid & 3;              // chunk 0..3

    float acc[4][4][4];
#pragma unroll
    for (int i = 0; i < 4; ++i)
#pragma unroll
        for (int j = 0; j < 4; ++j)
#pragma unroll
            for (int q = 0; q < 4; ++q) acc[i][j][q] = 0.f;

    auto issue = [&](int it) {
        const int k0 = it * 32;
        const int buf = it % NSTAGE;
        const __half* Ab;
        int astr;
        if (k0 < 1024) { Ab = Sg + (size_t)by * 1024 + k0; astr = 1024; }
        else           { Ab = Rg + (size_t)by * 256 + (k0 - 1024); astr = 256; }
        const uint32_t dA = smem_base + buf * STAGE_HALFS * 2;
        const uint32_t dB = dA + 64 * PITCH * 2;
        cp_async16(dA + (r16 * PITCH + c16 * 8) * 2, Ab + (size_t)r16 * astr + c16 * 8);
#pragma unroll
        for (int p = 0; p < 4; ++p) {
            int n = r16 + p * 64;
            cp_async16(dB + (n * PITCH + c16 * 8) * 2,
                       WT + (size_t)n * KTOT + k0 + c16 * 8);
        }
        asm volatile("cp.async.commit_group;\n" ::);
    };

    issue(0);
    issue(1);

    for (int it = 0; it < NIT; ++it) {
        if (it == NIT - 1) asm volatile("cp.async.wait_group 0;\n" ::);
        else               asm volatile("cp.async.wait_group 1;\n" ::);
        __syncthreads();
        if (it + 2 < NIT) issue(it + 2);

        const int buf = it % NSTAGE;
        const uint32_t cA = smem_base + buf * STAGE_HALFS * 2 + a_lane;
        const uint32_t cB = smem_base + buf * STAGE_HALFS * 2 + 64 * PITCH * 2 + b_lane;

#pragma unroll
        for (int kk = 0; kk < 32; kk += 16) {
            uint32_t af[4][4], bf[4][2];
#pragma unroll
            for (int mi = 0; mi < 4; ++mi)
                ldsm_x4(af[mi][0], af[mi][1], af[mi][2], af[mi][3],
                        cA + (mi * 16 * PITCH + kk) * 2);
#pragma unroll
            for (int nb = 0; nb < 2; ++nb)
                ldsm_x4(bf[2 * nb][0], bf[2 * nb][1], bf[2 * nb + 1][0], bf[2 * nb + 1][1],
                        cB + (nb * 16 * PITCH + kk) * 2);
#pragma unroll
            for (int mi = 0; mi < 4; ++mi)
#pragma unroll
                for (int ni = 0; ni < 4; ++ni)
                    mma_fp16(acc[mi][ni], af[mi], bf[ni]);
        }
    }

    // epilogue
#pragma unroll
    for (int mi = 0; mi < 4; ++mi) {
        const int row = by + mi * 16 + g;
#pragma unroll
        for (int ni = 0; ni < 4; ++ni) {
            const int col = wn * 32 + ni * 8 + t4 * 2;
            const float b0 = g_bias[layer][col];
            const float b1 = g_bias[layer][col + 1];
            float v0 = acc[mi][ni][0] + b0, v1 = acc[mi][ni][1] + b1;
            float v2 = acc[mi][ni][2] + b0, v3 = acc[mi][ni][3] + b1;
            if (layer == 0) {
                v0 = fmaxf(v0, 0.f); v1 = fmaxf(v1, 0.f);
                v2 = fmaxf(v2, 0.f); v3 = fmaxf(v3, 0.f);
                *(__half2*)(g_h1h + (size_t)row * 256 + col)       = __floats2half2_rn(v0, v1);
                *(__half2*)(g_h1h + (size_t)(row + 8) * 256 + col) = __floats2half2_rn(v2, v3);
            } else {
                *(float2*)(out_ext + (size_t)row * 256 + col)       = make_float2(v0, v1);
                *(float2*)(out_ext + (size_t)(row + 8) * 256 + col) = make_float2(v2, v3);
            }
        }
    }
}

// ---------------- launch ----------------
extern "C" void kernel_launch(void* const* d_in, const int* in_sizes, int n_in,
                              void* d_out, int out_size) {
    const float* x      = (const float*)d_in[0];
    const int*   edges  = (const int*)d_in[3];
    const int*   rel    = (const int*)d_in[4];
    const float* basis0 = (const float*)d_in[5];
    const float* comp0  = (const float*)d_in[6];
    const float* root0  = (const float*)d_in[7];
    const float* bias0  = (const float*)d_in[8];
    const float* basis1 = (const float*)d_in[9];
    const float* comp1  = (const float*)d_in[10];
    const float* root1  = (const float*)d_in[11];
    const float* bias1  = (const float*)d_in[12];
    float* out = (float*)d_out;

    const int* src = edges;
    const int* dst = edges + NEDGES;

    // one-time side objects (created on first call, before graph capture; no device mem)
    static cudaStream_t s2 = [] {
        cudaStream_t s;
        cudaStreamCreateWithFlags(&s, cudaStreamNonBlocking);
        return s;
    }();
    static cudaEvent_t evFork = [] {
        cudaEvent_t e;
        cudaEventCreateWithFlags(&e, cudaEventDisableTiming);
        return e;
    }();
    static cudaEvent_t evJoin = [] {
        cudaEvent_t e;
        cudaEventCreateWithFlags(&e, cudaEventDisableTiming);
        return e;
    }();
    static bool attr_set = [] {
        cudaFuncSetAttribute(gemm_fp16_kernel,
                             cudaFuncAttributeMaxDynamicSharedMemorySize, GEMM_SMEM);
        return true;
    }();
    (void)attr_set;

    // Fork: CSR chain on s2, operand prep on the main (captured) stream.
    cudaEventRecord(evFork, 0);
    cudaStreamWaitEvent(s2, evFork, 0);

    zero_counts_kernel<<<(NREL * NNODES + 255) / 256, 256, 0, s2>>>();
    hist_kernel<<<(NEDGES + 255) / 256, 256, 0, s2>>>(dst, rel);
    scan1_kernel<<<NNODES / 1024, 1024, 0, s2>>>();
    scan3_kernel<<<NNODES / 1024, 1024, 0, s2>>>();
    scatter_kernel<<<(NEDGES + 255) / 256, 256, 0, s2>>>(src, dst, rel);
    expand_kernel<<<(NEDGES + 255) / 256, 256, 0, s2>>>(comp0, comp1);
    cudaEventRecord(evJoin, s2);

    prep_kernel<<<(NNODES * D + 255) / 256, 256>>>(x, basis0, root0, basis1, root1,
                                                   bias0, bias1);

    // Join before aggregation needs both chains.
    cudaStreamWaitEvent(0, evJoin, 0);

    // Layer 0: aggregate(x) -> S; [S|x] @ W0 + bias0, ReLU -> h1
    aggregate_kernel<<<NNODES / 8, 512>>>(0);
    gemm_fp16_kernel<<<NNODES / 64, 256, GEMM_SMEM>>>(nullptr, 0);

    // Layer 1: aggregate(h1) -> S; [S|h1] @ W1 + bias1 -> out
    aggregate_kernel<<<NNODES / 8, 512>>>(1);
    gemm_fp16_kernel<<<NNODES / 64, 256, GEMM_SMEM>>>(out, 1);
}

// round 16
// speedup vs baseline: 1.8669x; 1.2067x over previous
#include <cuda_runtime.h>
#include <cuda_fp16.h>
#include <cstdint>

#define D 256
#define NNODES 32768
#define NREL 10
#define NBASES 4
#define NEDGES 524288
#define KTOT 1280          // 1024 (basis-agg part) + 256 (root part)

// ---------------- scratch (static device allocations; no cudaMalloc) ----------------
__device__ __half  g_Sh[(size_t)NNODES * 1024];  // 64 MB: aggregated basis sums (fp16)
__device__ __half  g_h1h[(size_t)NNODES * D];    // 16 MB: hidden activations (fp16)
__device__ __half  g_xh[(size_t)NNODES * D];     // 16 MB: fp16 input x
__device__ __half  g_W0T[D * KTOT];              // W^T layer0: [n=256][k=1280] (fp16)
__device__ __half  g_W1T[D * KTOT];              // W^T layer1
__device__ float   g_bias[2][D];
__device__ int     g_cnt[NREL * NNODES];
__device__ int     g_rowptr[NNODES + 1];
__device__ int     g_cursor[NNODES];
__device__ int     g_part[32];
__device__ uint2   g_ep[NEDGES];                 // per-edge: {src | rel<<16, f32 inv}
__device__ int     g_csr_src[NEDGES];
__device__ float4  g_ew0[NEDGES];
__device__ float4  g_ew1[NEDGES];

// ---------------- helpers ----------------
__device__ __forceinline__ void cp_async16(uint32_t saddr, const void* gaddr) {
    asm volatile("cp.async.cg.shared.global [%0], [%1], 16;\n" :: "r"(saddr), "l"(gaddr));
}

__device__ __forceinline__ void mma_fp16(float* d, const uint32_t* a, const uint32_t* b) {
    asm volatile(
        "mma.sync.aligned.m16n8k16.row.col.f32.f16.f16.f32 "
        "{%0,%1,%2,%3}, {%4,%5,%6,%7}, {%8,%9}, {%0,%1,%2,%3};\n"
        : "+f"(d[0]), "+f"(d[1]), "+f"(d[2]), "+f"(d[3])
        : "r"(a[0]), "r"(a[1]), "r"(a[2]), "r"(a[3]), "r"(b[0]), "r"(b[1]));
}

__device__ __forceinline__ void ldsm_x4(uint32_t& r0, uint32_t& r1, uint32_t& r2,
                                        uint32_t& r3, uint32_t saddr) {
    asm volatile("ldmatrix.sync.aligned.m8n8.x4.shared.b16 {%0,%1,%2,%3}, [%4];"
                 : "=r"(r0), "=r"(r1), "=r"(r2), "=r"(r3) : "r"(saddr));
}

__device__ __forceinline__ void ffma2(uint64_t& acc, uint64_t a, uint64_t b) {
    asm("fma.rn.f32x2 %0, %1, %2, %0;" : "+l"(acc) : "l"(a), "l"(b));
}

__device__ __forceinline__ uint64_t packf2(float lo, float hi) {
    uint64_t v;
    asm("mov.b64 %0, {%1, %2};" : "=l"(v) : "f"(lo), "f"(hi));
    return v;
}

__device__ __forceinline__ float2 unpackf2(uint64_t v) {
    float2 o;
    asm("mov.b64 {%0, %1}, %2;" : "=f"(o.x), "=f"(o.y) : "l"(v));
    return o;
}

__device__ __forceinline__ uint32_t pack2h(float x, float y) {
    __half2 p = __floats2half2_rn(x, y);
    return *(uint32_t*)&p;
}

// ---------------- zero the (rel,dst) histogram ----------------
__global__ void zero_counts_kernel() {
    int i = blockIdx.x * blockDim.x + threadIdx.x;
    if (i < NREL * NNODES) g_cnt[i] = 0;
}

// ---------------- histogram (one atomic per edge) ----------------
__global__ void hist_kernel(const int* __restrict__ dst, const int* __restrict__ rel) {
    int e = blockIdx.x * blockDim.x + threadIdx.x;
    if (e >= NEDGES) return;
    atomicAdd(&g_cnt[rel[e] * NNODES + dst[e]], 1);
}

// ---------------- parallel scan, phase 1: per-block exclusive scan of degrees ------
__global__ __launch_bounds__(1024) void scan1_kernel() {
    __shared__ int s[1024];
    const int t = threadIdx.x;
    const int i = blockIdx.x * 1024 + t;
    int deg = 0;
#pragma unroll
    for (int r = 0; r < NREL; ++r) deg += g_cnt[r * NNODES + i];
    s[t] = deg;
    __syncthreads();
    for (int off = 1; off < 1024; off <<= 1) {
        int v = 0;
        if (t >= off) v = s[t - off];
        __syncthreads();
        if (t >= off) s[t] += v;
        __syncthreads();
    }
    g_rowptr[i] = (t == 0) ? 0 : s[t - 1];      // block-local exclusive
    if (t == 1023) g_part[blockIdx.x] = s[1023];
}

// ---------------- phase 2: redundant warp-scan of partials + add offsets -----------
__global__ __launch_bounds__(1024) void scan3_kernel() {
    __shared__ int s_off;
    if (threadIdx.x < 32) {
        int v = g_part[threadIdx.x];
        int incl = v;
#pragma unroll
        for (int o = 1; o < 32; o <<= 1) {
            int n = __shfl_up_sync(0xFFFFFFFF, incl, o);
            if ((int)threadIdx.x >= o) incl += n;
        }
        if (threadIdx.x == 31 && blockIdx.x == 0) g_rowptr[NNODES] = incl;
        if ((int)threadIdx.x == (int)blockIdx.x) s_off = incl - v;   // exclusive offset
    }
    __syncthreads();
    const int i = blockIdx.x * 1024 + threadIdx.x;
    int v = g_rowptr[i] + s_off;
    g_rowptr[i] = v;
    g_cursor[i] = v;
}

// ---------------- scatter: packed (src,rel,inv) in CSR(dst) order (8B/edge) --------
__global__ void scatter_kernel(const int* __restrict__ src, const int* __restrict__ dst,
                               const int* __restrict__ rel) {
    int e = blockIdx.x * blockDim.x + threadIdx.x;
    if (e >= NEDGES) return;
    int d = dst[e];
    int r = rel[e];
    int p = atomicAdd(&g_cursor[d], 1);
    float inv = 1.0f / (float)g_cnt[r * NNODES + d];
    g_ep[p] = make_uint2((uint32_t)src[e] | ((uint32_t)r << 16), __float_as_uint(inv));
}

// ---------------- expand: coalesced materialization of src + per-edge weights ------
__global__ void expand_kernel(const float* __restrict__ comp0,
                              const float* __restrict__ comp1) {
    int e = blockIdx.x * blockDim.x + threadIdx.x;
    if (e >= NEDGES) return;
    uint2 ep = g_ep[e];
    int r = ep.x >> 16;
    float inv = __uint_as_float(ep.y);
    g_csr_src[e] = (int)(ep.x & 0xFFFF);
    g_ew0[e] = make_float4(comp0[r * 4 + 0] * inv, comp0[r * 4 + 1] * inv,
                           comp0[r * 4 + 2] * inv, comp0[r * 4 + 3] * inv);
    g_ew1[e] = make_float4(comp1[r * 4 + 0] * inv, comp1[r * 4 + 1] * inv,
                           comp1[r * 4 + 2] * inv, comp1[r * 4 + 3] * inv);
}

// ---------------- fused prep: x->fp16, W^T (both layers), bias ---------------------
__global__ void prep_kernel(const float* __restrict__ x,
                            const float* __restrict__ basis0, const float* __restrict__ root0,
                            const float* __restrict__ basis1, const float* __restrict__ root1,
                            const float* __restrict__ bias0, const float* __restrict__ bias1) {
    int i = blockIdx.x * blockDim.x + threadIdx.x;
    if (i < NNODES * D) g_xh[i] = __float2half_rn(x[i]);
    if (i < D * KTOT) {
        int n = i / KTOT;
        int k = i % KTOT;
        float v0, v1;
        if (k < NBASES * D) {
            int b = k >> 8;
            int r = k & 255;
            v0 = basis0[((size_t)b * D + r) * D + n];
            v1 = basis1[((size_t)b * D + r) * D + n];
        } else {
            v0 = root0[(size_t)(k - NBASES * D) * D + n];
            v1 = root1[(size_t)(k - NBASES * D) * D + n];
        }
        g_W0T[i] = __float2half_rn(v0);
        g_W1T[i] = __float2half_rn(v1);
    }
    if (i < D) { g_bias[0][i] = bias0[i]; g_bias[1][i] = bias1[i]; }
}

// ---------------- aggregation: S[dst, b, :] = sum_e w_b(e) feat[src] ----------------
// ONE warp per dst (32 threads x 8 cols via uint4): halves warp-load instructions.
// 512 threads per block = 16 dst nodes; packed f32x2 FFMA2 accumulation (exact).
__global__ __launch_bounds__(512) void aggregate_kernel(int layer) {
    const uint4* __restrict__ featv = (const uint4*)(layer ? g_h1h : g_xh);
    const float4* __restrict__ ew   = layer ? g_ew1 : g_ew0;
    const int dst = blockIdx.x * 16 + (threadIdx.x >> 5);
    const int t = threadIdx.x & 31;   // each owns 8 columns (uint4 = 8 halfs)

    uint64_t acc[4][4] = {};          // 4 bases x 4 packed f32x2 (8 cols)
    const int beg = g_rowptr[dst];
    const int end = g_rowptr[dst + 1];
    int e = beg;

    auto accum = [&](const float4& wt, const uint4& u) {
        float2 f01 = __half22float2(*(const __half2*)&u.x);
        float2 f23 = __half22float2(*(const __half2*)&u.y);
        float2 f45 = __half22float2(*(const __half2*)&u.z);
        float2 f67 = __half22float2(*(const __half2*)&u.w);
        uint64_t v01 = packf2(f01.x, f01.y);
        uint64_t v23 = packf2(f23.x, f23.y);
        uint64_t v45 = packf2(f45.x, f45.y);
        uint64_t v67 = packf2(f67.x, f67.y);
        uint64_t w0 = packf2(wt.x, wt.x);
        uint64_t w1 = packf2(wt.y, wt.y);
        uint64_t w2 = packf2(wt.z, wt.z);
        uint64_t w3 = packf2(wt.w, wt.w);
        ffma2(acc[0][0], w0, v01); ffma2(acc[0][1], w0, v23);
        ffma2(acc[0][2], w0, v45); ffma2(acc[0][3], w0, v67);
        ffma2(acc[1][0], w1, v01); ffma2(acc[1][1], w1, v23);
        ffma2(acc[1][2], w1, v45); ffma2(acc[1][3], w1, v67);
        ffma2(acc[2][0], w2, v01); ffma2(acc[2][1], w2, v23);
        ffma2(acc[2][2], w2, v45); ffma2(acc[2][3], w2, v67);
        ffma2(acc[3][0], w3, v01); ffma2(acc[3][1], w3, v23);
        ffma2(acc[3][2], w3, v45); ffma2(acc[3][3], w3, v67);
    };

    for (; e + 4 <= end; e += 4) {
        const int s0 = __ldg(&g_csr_src[e + 0]);
        const int s1 = __ldg(&g_csr_src[e + 1]);
        const int s2 = __ldg(&g_csr_src[e + 2]);
        const int s3 = __ldg(&g_csr_src[e + 3]);
        const uint4 u0 = __ldg(&featv[(size_t)s0 * 32 + t]);
        const uint4 u1 = __ldg(&featv[(size_t)s1 * 32 + t]);
        const uint4 u2 = __ldg(&featv[(size_t)s2 * 32 + t]);
        const uint4 u3 = __ldg(&featv[(size_t)s3 * 32 + t]);
        const float4 w0 = __ldg(&ew[e + 0]);
        const float4 w1 = __ldg(&ew[e + 1]);
        const float4 w2 = __ldg(&ew[e + 2]);
        const float4 w3 = __ldg(&ew[e + 3]);
        accum(w0, u0);
        accum(w1, u1);
        accum(w2, u2);
        accum(w3, u3);
    }
    for (; e < end; ++e) {
        const int s = __ldg(&g_csr_src[e]);
        const float4 wt = __ldg(&ew[e]);
        const uint4 u = __ldg(&featv[(size_t)s * 32 + t]);
        accum(wt, u);
    }

    uint4* Sp = (uint4*)(g_Sh + (size_t)dst * 1024);   // 128 uint4 per row
#pragma unroll
    for (int b = 0; b < 4; ++b) {
        float2 c01 = unpackf2(acc[b][0]);
        float2 c23 = unpackf2(acc[b][1]);
        float2 c45 = unpackf2(acc[b][2]);
        float2 c67 = unpackf2(acc[b][3]);
        uint4 o;
        o.x = pack2h(c01.x, c01.y);
        o.y = pack2h(c23.x, c23.y);
        o.z = pack2h(c45.x, c45.y);
        o.w = pack2h(c67.x, c67.y);
        Sp[b * 32 + t] = o;
    }
}

// ---------------- fp16 tensor-core GEMM (mma.sync.m16n8k16 + ldmatrix) ------------
// C[32768,256] = A[32768,1280] @ W[1280,256] (+bias, opt relu)
// M=64 rows per CTA, full N=256: 256 threads (8 warps, 1M x 8N), warp tile 64x32.
// 2 CTAs/SM co-resident. 3-stage cp.async, LDSM fragments.
#define PITCH 40                               // halfs per smem row (32 + 8 pad)
#define STAGE_HALFS ((64 + 256) * PITCH)       // A[64][40] + B[256][40] = 12800
#define NSTAGE 3
#define NIT (KTOT / 32)                        // 40
#define GEMM_SMEM (NSTAGE * STAGE_HALFS * 2)   // 76800 bytes

__global__ __launch_bounds__(256, 2) void gemm_fp16_kernel(float* __restrict__ out_ext, int layer) {
    extern __shared__ __half smem[];

    const __half* __restrict__ Sg = g_Sh;
    const __half* __restrict__ Rg = layer ? g_h1h : g_xh;
    const __half* __restrict__ WT = layer ? g_W1T : g_W0T;

    const int tid  = threadIdx.x;
    const int warp = tid >> 5, lane = tid & 31;
    const int g  = lane >> 2, t4 = lane & 3;
    const int wn = warp;                       // 8 warps across N
    const int by = blockIdx.x * 64;

    const uint32_t smem_base = (uint32_t)__cvta_generic_to_shared(smem);

    // ldmatrix per-lane byte offsets within a stage:
    const uint32_t a_lane = (uint32_t)((((lane & 7) + ((lane >> 3) & 1) * 8) * PITCH
                                        + (lane >> 4) * 8) * 2);
    const uint32_t b_lane = (uint32_t)(((wn * 32 + (lane >> 4) * 8 + (lane & 7)) * PITCH
                                        + ((lane >> 3) & 1) * 8) * 2);

    // gmem->smem: 16B units. A: 256 units (1/thread). B: 1024 units (4/thread).
    const int r16 = tid >> 2;             // 0..63
    const int c16 = tid & 3;              // chunk 0..3

    float acc[4][4][4];
#pragma unroll
    for (int i = 0; i < 4; ++i)
#pragma unroll
        for (int j = 0; j < 4; ++j)
#pragma unroll
            for (int q = 0; q < 4; ++q) acc[i][j][q] = 0.f;

    auto issue = [&](int it) {
        const int k0 = it * 32;
        const int buf = it % NSTAGE;
        const __half* Ab;
        int astr;
        if (k0 < 1024) { Ab = Sg + (size_t)by * 1024 + k0; astr = 1024; }
        else           { Ab = Rg + (size_t)by * 256 + (k0 - 1024); astr = 256; }
        const uint32_t dA = smem_base + buf * STAGE_HALFS * 2;
        const uint32_t dB = dA + 64 * PITCH * 2;
        cp_async16(dA + (r16 * PITCH + c16 * 8) * 2, Ab + (size_t)r16 * astr + c16 * 8);
#pragma unroll
        for (int p = 0; p < 4; ++p) {
            int n = r16 + p * 64;
            cp_async16(dB + (n * PITCH + c16 * 8) * 2,
                       WT + (size_t)n * KTOT + k0 + c16 * 8);
        }
        asm volatile("cp.async.commit_group;\n" ::);
    };

    issue(0);
    issue(1);

    for (int it = 0; it < NIT; ++it) {
        if (it == NIT - 1) asm volatile("cp.async.wait_group 0;\n" ::);
        else               asm volatile("cp.async.wait_group 1;\n" ::);
        __syncthreads();
        if (it + 2 < NIT) issue(it + 2);

        const int buf = it % NSTAGE;
        const uint32_t cA = smem_base + buf * STAGE_HALFS * 2 + a_lane;
        const uint32_t cB = smem_base + buf * STAGE_HALFS * 2 + 64 * PITCH * 2 + b_lane;

#pragma unroll
        for (int kk = 0; kk < 32; kk += 16) {
            uint32_t af[4][4], bf[4][2];
#pragma unroll
            for (int mi = 0; mi < 4; ++mi)
                ldsm_x4(af[mi][0], af[mi][1], af[mi][2], af[mi][3],
                        cA + (mi * 16 * PITCH + kk) * 2);
#pragma unroll
            for (int nb = 0; nb < 2; ++nb)
                ldsm_x4(bf[2 * nb][0], bf[2 * nb][1], bf[2 * nb + 1][0], bf[2 * nb + 1][1],
                        cB + (nb * 16 * PITCH + kk) * 2);
#pragma unroll
            for (int mi = 0; mi < 4; ++mi)
#pragma unroll
                for (int ni = 0; ni < 4; ++ni)
                    mma_fp16(acc[mi][ni], af[mi], bf[ni]);
        }
    }

    // epilogue
#pragma unroll
    for (int mi = 0; mi < 4; ++mi) {
        const int row = by + mi * 16 + g;
#pragma unroll
        for (int ni = 0; ni < 4; ++ni) {
            const int col = wn * 32 + ni * 8 + t4 * 2;
            const float b0 = g_bias[layer][col];
            const float b1 = g_bias[layer][col + 1];
            float v0 = acc[mi][ni][0] + b0, v1 = acc[mi][ni][1] + b1;
            float v2 = acc[mi][ni][2] + b0, v3 = acc[mi][ni][3] + b1;
            if (layer == 0) {
                v0 = fmaxf(v0, 0.f); v1 = fmaxf(v1, 0.f);
                v2 = fmaxf(v2, 0.f); v3 = fmaxf(v3, 0.f);
                *(__half2*)(g_h1h + (size_t)row * 256 + col)       = __floats2half2_rn(v0, v1);
                *(__half2*)(g_h1h + (size_t)(row + 8) * 256 + col) = __floats2half2_rn(v2, v3);
            } else {
                *(float2*)(out_ext + (size_t)row * 256 + col)       = make_float2(v0, v1);
                *(float2*)(out_ext + (size_t)(row + 8) * 256 + col) = make_float2(v2, v3);
            }
        }
    }
}

// ---------------- launch ----------------
extern "C" void kernel_launch(void* const* d_in, const int* in_sizes, int n_in,
                              void* d_out, int out_size) {
    const float* x      = (const float*)d_in[0];
    const int*   edges  = (const int*)d_in[3];
    const int*   rel    = (const int*)d_in[4];
    const float* basis0 = (const float*)d_in[5];
    const float* comp0  = (const float*)d_in[6];
    const float* root0  = (const float*)d_in[7];
    const float* bias0  = (const float*)d_in[8];
    const float* basis1 = (const float*)d_in[9];
    const float* comp1  = (const float*)d_in[10];
    const float* root1  = (const float*)d_in[11];
    const float* bias1  = (const float*)d_in[12];
    float* out = (float*)d_out;

    const int* src = edges;
    const int* dst = edges + NEDGES;

    // one-time side objects (created on first call, before graph capture; no device mem)
    static cudaStream_t s2 = [] {
        cudaStream_t s;
        cudaStreamCreateWithFlags(&s, cudaStreamNonBlocking);
        return s;
    }();
    static cudaEvent_t evFork = [] {
        cudaEvent_t e;
        cudaEventCreateWithFlags(&e, cudaEventDisableTiming);
        return e;
    }();
    static cudaEvent_t evJoin = [] {
        cudaEvent_t e;
        cudaEventCreateWithFlags(&e, cudaEventDisableTiming);
        return e;
    }();
    static bool attr_set = [] {
        cudaFuncSetAttribute(gemm_fp16_kernel,
                             cudaFuncAttributeMaxDynamicSharedMemorySize, GEMM_SMEM);
        return true;
    }();
    (void)attr_set;

    // Fork: CSR chain on s2, operand prep on the main (captured) stream.
    cudaEventRecord(evFork, 0);
    cudaStreamWaitEvent(s2, evFork, 0);

    zero_counts_kernel<<<(NREL * NNODES + 255) / 256, 256, 0, s2>>>();
    hist_kernel<<<(NEDGES + 255) / 256, 256, 0, s2>>>(dst, rel);
    scan1_kernel<<<NNODES / 1024, 1024, 0, s2>>>();
    scan3_kernel<<<NNODES / 1024, 1024, 0, s2>>>();
    scatter_kernel<<<(NEDGES + 255) / 256, 256, 0, s2>>>(src, dst, rel);
    expand_kernel<<<(NEDGES + 255) / 256, 256, 0, s2>>>(comp0, comp1);
    cudaEventRecord(evJoin, s2);

    prep_kernel<<<(NNODES * D + 255) / 256, 256>>>(x, basis0, root0, basis1, root1,
                                                   bias0, bias1);

    // Join before aggregation needs both chains.
    cudaStreamWaitEvent(0, evJoin, 0);

    // Layer 0: aggregate(x) -> S; [S|x] @ W0 + bias0, ReLU -> h1
    aggregate_kernel<<<NNODES / 16, 512>>>(0);
    gemm_fp16_kernel<<<NNODES / 64, 256, GEMM_SMEM>>>(nullptr, 0);

    // Layer 1: aggregate(h1) -> S; [S|h1] @ W1 + bias1 -> out
    aggregate_kernel<<<NNODES / 16, 512>>>(1);
    gemm_fp16_kernel<<<NNODES / 64, 256, GEMM_SMEM>>>(out, 1);
}

// round 17
// speedup vs baseline: 1.8881x; 1.0114x over previous
#include <cuda_runtime.h>
#include <cuda_fp16.h>
#include <cstdint>

#define D 256
#define NNODES 32768
#define NREL 10
#define NBASES 4
#define NEDGES 524288
#define KTOT 1280          // 1024 (basis-agg part) + 256 (root part)

// ---------------- scratch (static device allocations; no cudaMalloc) ----------------
__device__ __half  g_Sh[(size_t)NNODES * 1024];  // 64 MB: aggregated basis sums (fp16)
__device__ __half  g_h1h[(size_t)NNODES * D];    // 16 MB: hidden activations (fp16)
__device__ __half  g_xh[(size_t)NNODES * D];     // 16 MB: fp16 input x
__device__ __half  g_W0T[D * KTOT];              // W^T layer0: [n=256][k=1280] (fp16)
__device__ __half  g_W1T[D * KTOT];              // W^T layer1
__device__ float   g_bias[2][D];
__device__ float   g_comp[2][NREL * NBASES];     // comp coefficients, both layers
__device__ int     g_cnt[NREL * NNODES];
__device__ int     g_rowptr[NNODES + 1];
__device__ int     g_cursor[NNODES];
__device__ int     g_part[32];
__device__ uint2   g_ep[NEDGES];                 // per-edge: {src | rel<<16, f32 inv}

// ---------------- helpers ----------------
__device__ __forceinline__ void cp_async16(uint32_t saddr, const void* gaddr) {
    asm volatile("cp.async.cg.shared.global [%0], [%1], 16;\n" :: "r"(saddr), "l"(gaddr));
}

__device__ __forceinline__ void mma_fp16(float* d, const uint32_t* a, const uint32_t* b) {
    asm volatile(
        "mma.sync.aligned.m16n8k16.row.col.f32.f16.f16.f32 "
        "{%0,%1,%2,%3}, {%4,%5,%6,%7}, {%8,%9}, {%0,%1,%2,%3};\n"
        : "+f"(d[0]), "+f"(d[1]), "+f"(d[2]), "+f"(d[3])
        : "r"(a[0]), "r"(a[1]), "r"(a[2]), "r"(a[3]), "r"(b[0]), "r"(b[1]));
}

__device__ __forceinline__ void ldsm_x4(uint32_t& r0, uint32_t& r1, uint32_t& r2,
                                        uint32_t& r3, uint32_t saddr) {
    asm volatile("ldmatrix.sync.aligned.m8n8.x4.shared.b16 {%0,%1,%2,%3}, [%4];"
                 : "=r"(r0), "=r"(r1), "=r"(r2), "=r"(r3) : "r"(saddr));
}

__device__ __forceinline__ void ffma2(uint64_t& acc, uint64_t a, uint64_t b) {
    asm("fma.rn.f32x2 %0, %1, %2, %0;" : "+l"(acc) : "l"(a), "l"(b));
}

__device__ __forceinline__ uint64_t packf2(float lo, float hi) {
    uint64_t v;
    asm("mov.b64 %0, {%1, %2};" : "=l"(v) : "f"(lo), "f"(hi));
    return v;
}

__device__ __forceinline__ float2 unpackf2(uint64_t v) {
    float2 o;
    asm("mov.b64 {%0, %1}, %2;" : "=f"(o.x), "=f"(o.y) : "l"(v));
    return o;
}

__device__ __forceinline__ uint32_t pack2h(float x, float y) {
    __half2 p = __floats2half2_rn(x, y);
    return *(uint32_t*)&p;
}

// ---------------- zero the (rel,dst) histogram ----------------
__global__ void zero_counts_kernel() {
    int i = blockIdx.x * blockDim.x + threadIdx.x;
    if (i < NREL * NNODES) g_cnt[i] = 0;
}

// ---------------- histogram (one atomic per edge) ----------------
__global__ void hist_kernel(const int* __restrict__ dst, const int* __restrict__ rel) {
    int e = blockIdx.x * blockDim.x + threadIdx.x;
    if (e >= NEDGES) return;
    atomicAdd(&g_cnt[rel[e] * NNODES + dst[e]], 1);
}

// ---------------- parallel scan, phase 1: per-block exclusive scan of degrees ------
__global__ __launch_bounds__(1024) void scan1_kernel() {
    __shared__ int s[1024];
    const int t = threadIdx.x;
    const int i = blockIdx.x * 1024 + t;
    int deg = 0;
#pragma unroll
    for (int r = 0; r < NREL; ++r) deg += g_cnt[r * NNODES + i];
    s[t] = deg;
    __syncthreads();
    for (int off = 1; off < 1024; off <<= 1) {
        int v = 0;
        if (t >= off) v = s[t - off];
        __syncthreads();
        if (t >= off) s[t] += v;
        __syncthreads();
    }
    g_rowptr[i] = (t == 0) ? 0 : s[t - 1];      // block-local exclusive
    if (t == 1023) g_part[blockIdx.x] = s[1023];
}

// ---------------- phase 2: redundant warp-scan of partials + add offsets -----------
__global__ __launch_bounds__(1024) void scan3_kernel() {
    __shared__ int s_off;
    if (threadIdx.x < 32) {
        int v = g_part[threadIdx.x];
        int incl = v;
#pragma unroll
        for (int o = 1; o < 32; o <<= 1) {
            int n = __shfl_up_sync(0xFFFFFFFF, incl, o);
            if ((int)threadIdx.x >= o) incl += n;
        }
        if (threadIdx.x == 31 && blockIdx.x == 0) g_rowptr[NNODES] = incl;
        if ((int)threadIdx.x == (int)blockIdx.x) s_off = incl - v;   // exclusive offset
    }
    __syncthreads();
    const int i = blockIdx.x * 1024 + threadIdx.x;
    int v = g_rowptr[i] + s_off;
    g_rowptr[i] = v;
    g_cursor[i] = v;
}

// ---------------- scatter: packed (src,rel,inv) in CSR(dst) order (8B/edge) --------
__global__ void scatter_kernel(const int* __restrict__ src, const int* __restrict__ dst,
                               const int* __restrict__ rel) {
    int e = blockIdx.x * blockDim.x + threadIdx.x;
    if (e >= NEDGES) return;
    int d = dst[e];
    int r = rel[e];
    int p = atomicAdd(&g_cursor[d], 1);
    float inv = 1.0f / (float)g_cnt[r * NNODES + d];
    g_ep[p] = make_uint2((uint32_t)src[e] | ((uint32_t)r << 16), __float_as_uint(inv));
}

// ---------------- fused prep: x->fp16, W^T (both layers), bias, comp ---------------
__global__ void prep_kernel(const float* __restrict__ x,
                            const float* __restrict__ basis0, const float* __restrict__ root0,
                            const float* __restrict__ basis1, const float* __restrict__ root1,
                            const float* __restrict__ bias0, const float* __restrict__ bias1,
                            const float* __restrict__ comp0, const float* __restrict__ comp1) {
    int i = blockIdx.x * blockDim.x + threadIdx.x;
    if (i < NNODES * D) g_xh[i] = __float2half_rn(x[i]);
    if (i < D * KTOT) {
        int n = i / KTOT;
        int k = i % KTOT;
        float v0, v1;
        if (k < NBASES * D) {
            int b = k >> 8;
            int r = k & 255;
            v0 = basis0[((size_t)b * D + r) * D + n];
            v1 = basis1[((size_t)b * D + r) * D + n];
        } else {
            v0 = root0[(size_t)(k - NBASES * D) * D + n];
            v1 = root1[(size_t)(k - NBASES * D) * D + n];
        }
        g_W0T[i] = __float2half_rn(v0);
        g_W1T[i] = __float2half_rn(v1);
    }
    if (i < D) { g_bias[0][i] = bias0[i]; g_bias[1][i] = bias1[i]; }
    if (i < NREL * NBASES) { g_comp[0][i] = comp0[i]; g_comp[1][i] = comp1[i]; }
}

// ---------------- aggregation: S[dst, b, :] = sum_e w_b(e) feat[src] ----------------
// ONE warp per dst (32 threads x 8 cols via uint4); per-edge weights reconstructed
// from SMEM comp (identical fp32 arithmetic to the old expand kernel).
// 512 threads per block = 16 dst nodes; packed f32x2 FFMA2 accumulation (exact).
__global__ __launch_bounds__(512) void aggregate_kernel(int layer) {
    const uint4* __restrict__ featv = (const uint4*)(layer ? g_h1h : g_xh);
    __shared__ float scomp[NREL * NBASES];
    if (threadIdx.x < NREL * NBASES) scomp[threadIdx.x] = g_comp[layer][threadIdx.x];
    __syncthreads();

    const int dst = blockIdx.x * 16 + (threadIdx.x >> 5);
    const int t = threadIdx.x & 31;   // each owns 8 columns (uint4 = 8 halfs)

    uint64_t acc[4][4] = {};          // 4 bases x 4 packed f32x2 (8 cols)
    const int beg = g_rowptr[dst];
    const int end = g_rowptr[dst + 1];
    int e = beg;

    auto accum = [&](uint2 ep, const uint4& u) {
        const int r = ep.x >> 16;
        const float inv = __uint_as_float(ep.y);
        float2 f01 = __half22float2(*(const __half2*)&u.x);
        float2 f23 = __half22float2(*(const __half2*)&u.y);
        float2 f45 = __half22float2(*(const __half2*)&u.z);
        float2 f67 = __half22float2(*(const __half2*)&u.w);
        uint64_t v01 = packf2(f01.x, f01.y);
        uint64_t v23 = packf2(f23.x, f23.y);
        uint64_t v45 = packf2(f45.x, f45.y);
        uint64_t v67 = packf2(f67.x, f67.y);
        float w0s = scomp[r * 4 + 0] * inv;
        float w1s = scomp[r * 4 + 1] * inv;
        float w2s = scomp[r * 4 + 2] * inv;
        float w3s = scomp[r * 4 + 3] * inv;
        uint64_t w0 = packf2(w0s, w0s);
        uint64_t w1 = packf2(w1s, w1s);
        uint64_t w2 = packf2(w2s, w2s);
        uint64_t w3 = packf2(w3s, w3s);
        ffma2(acc[0][0], w0, v01); ffma2(acc[0][1], w0, v23);
        ffma2(acc[0][2], w0, v45); ffma2(acc[0][3], w0, v67);
        ffma2(acc[1][0], w1, v01); ffma2(acc[1][1], w1, v23);
        ffma2(acc[1][2], w1, v45); ffma2(acc[1][3], w1, v67);
        ffma2(acc[2][0], w2, v01); ffma2(acc[2][1], w2, v23);
        ffma2(acc[2][2], w2, v45); ffma2(acc[2][3], w2, v67);
        ffma2(acc[3][0], w3, v01); ffma2(acc[3][1], w3, v23);
        ffma2(acc[3][2], w3, v45); ffma2(acc[3][3], w3, v67);
    };

    for (; e + 4 <= end; e += 4) {
        const uint2 e0 = __ldg(&g_ep[e + 0]);
        const uint2 e1 = __ldg(&g_ep[e + 1]);
        const uint2 e2 = __ldg(&g_ep[e + 2]);
        const uint2 e3 = __ldg(&g_ep[e + 3]);
        const uint4 u0 = __ldg(&featv[(size_t)(e0.x & 0xFFFF) * 32 + t]);
        const uint4 u1 = __ldg(&featv[(size_t)(e1.x & 0xFFFF) * 32 + t]);
        const uint4 u2 = __ldg(&featv[(size_t)(e2.x & 0xFFFF) * 32 + t]);
        const uint4 u3 = __ldg(&featv[(size_t)(e3.x & 0xFFFF) * 32 + t]);
        accum(e0, u0);
        accum(e1, u1);
        accum(e2, u2);
        accum(e3, u3);
    }
    for (; e < end; ++e) {
        const uint2 ep = __ldg(&g_ep[e]);
        const uint4 u = __ldg(&featv[(size_t)(ep.x & 0xFFFF) * 32 + t]);
        accum(ep, u);
    }

    uint4* Sp = (uint4*)(g_Sh + (size_t)dst * 1024);   // 128 uint4 per row
#pragma unroll
    for (int b = 0; b < 4; ++b) {
        float2 c01 = unpackf2(acc[b][0]);
        float2 c23 = unpackf2(acc[b][1]);
        float2 c45 = unpackf2(acc[b][2]);
        float2 c67 = unpackf2(acc[b][3]);
        uint4 o;
        o.x = pack2h(c01.x, c01.y);
        o.y = pack2h(c23.x, c23.y);
        o.z = pack2h(c45.x, c45.y);
        o.w = pack2h(c67.x, c67.y);
        Sp[b * 32 + t] = o;
    }
}

// ---------------- fp16 tensor-core GEMM (mma.sync.m16n8k16 + ldmatrix) ------------
// C[32768,256] = A[32768,1280] @ W[1280,256] (+bias, opt relu)
// M=64 rows per CTA, full N=256: 256 threads (8 warps, 1M x 8N), warp tile 64x32.
// 2 CTAs/SM co-resident. 3-stage cp.async, LDSM fragments.
#define PITCH 40                               // halfs per smem row (32 + 8 pad)
#define STAGE_HALFS ((64 + 256) * PITCH)       // A[64][40] + B[256][40] = 12800
#define NSTAGE 3
#define NIT (KTOT / 32)                        // 40
#define GEMM_SMEM (NSTAGE * STAGE_HALFS * 2)   // 76800 bytes

__global__ __launch_bounds__(256, 2) void gemm_fp16_kernel(float* __restrict__ out_ext, int layer) {
    extern __shared__ __half smem[];

    const __half* __restrict__ Sg = g_Sh;
    const __half* __restrict__ Rg = layer ? g_h1h : g_xh;
    const __half* __restrict__ WT = layer ? g_W1T : g_W0T;

    const int tid  = threadIdx.x;
    const int warp = tid >> 5, lane = tid & 31;
    const int g  = lane >> 2, t4 = lane & 3;
    const int wn = warp;                       // 8 warps across N
    const int by = blockIdx.x * 64;

    const uint32_t smem_base = (uint32_t)__cvta_generic_to_shared(smem);

    // ldmatrix per-lane byte offsets within a stage:
    const uint32_t a_lane = (uint32_t)((((lane & 7) + ((lane >> 3) & 1) * 8) * PITCH
                                        + (lane >> 4) * 8) * 2);
    const uint32_t b_lane = (uint32_t)(((wn * 32 + (lane >> 4) * 8 + (lane & 7)) * PITCH
                                        + ((lane >> 3) & 1) * 8) * 2);

    // gmem->smem: 16B units. A: 256 units (1/thread). B: 1024 units (4/thread).
    const int r16 = tid >> 2;             // 0..63
    const int c16 = tid & 3;              // chunk 0..3

    float acc[4][4][4];
#pragma unroll
    for (int i = 0; i < 4; ++i)
#pragma unroll
        for (int j = 0; j < 4; ++j)
#pragma unroll
            for (int q = 0; q < 4; ++q) acc[i][j][q] = 0.f;

    auto issue = [&](int it) {
        const int k0 = it * 32;
        const int buf = it % NSTAGE;
        const __half* Ab;
        int astr;
        if (k0 < 1024) { Ab = Sg + (size_t)by * 1024 + k0; astr = 1024; }
        else           { Ab = Rg + (size_t)by * 256 + (k0 - 1024); astr = 256; }
        const uint32_t dA = smem_base + buf * STAGE_HALFS * 2;
        const uint32_t dB = dA + 64 * PITCH * 2;
        cp_async16(dA + (r16 * PITCH + c16 * 8) * 2, Ab + (size_t)r16 * astr + c16 * 8);
#pragma unroll
        for (int p = 0; p < 4; ++p) {
            int n = r16 + p * 64;
            cp_async16(dB + (n * PITCH + c16 * 8) * 2,
                       WT + (size_t)n * KTOT + k0 + c16 * 8);
        }
        asm volatile("cp.async.commit_group;\n" ::);
    };

    issue(0);
    issue(1);

    for (int it = 0; it < NIT; ++it) {
        if (it == NIT - 1) asm volatile("cp.async.wait_group 0;\n" ::);
        else               asm volatile("cp.async.wait_group 1;\n" ::);
        __syncthreads();
        if (it + 2 < NIT) issue(it + 2);

        const int buf = it % NSTAGE;
        const uint32_t cA = smem_base + buf * STAGE_HALFS * 2 + a_lane;
        const uint32_t cB = smem_base + buf * STAGE_HALFS * 2 + 64 * PITCH * 2 + b_lane;

#pragma unroll
        for (int kk = 0; kk < 32; kk += 16) {
            uint32_t af[4][4], bf[4][2];
#pragma unroll
            for (int mi = 0; mi < 4; ++mi)
                ldsm_x4(af[mi][0], af[mi][1], af[mi][2], af[mi][3],
                        cA + (mi * 16 * PITCH + kk) * 2);
#pragma unroll
            for (int nb = 0; nb < 2; ++nb)
                ldsm_x4(bf[2 * nb][0], bf[2 * nb][1], bf[2 * nb + 1][0], bf[2 * nb + 1][1],
                        cB + (nb * 16 * PITCH + kk) * 2);
#pragma unroll
            for (int mi = 0; mi < 4; ++mi)
#pragma unroll
                for (int ni = 0; ni < 4; ++ni)
                    mma_fp16(acc[mi][ni], af[mi], bf[ni]);
        }
    }

    // epilogue
#pragma unroll
    for (int mi = 0; mi < 4; ++mi) {
        const int row = by + mi * 16 + g;
#pragma unroll
        for (int ni = 0; ni < 4; ++ni) {
            const int col = wn * 32 + ni * 8 + t4 * 2;
            const float b0 = g_bias[layer][col];
            const float b1 = g_bias[layer][col + 1];
            float v0 = acc[mi][ni][0] + b0, v1 = acc[mi][ni][1] + b1;
            float v2 = acc[mi][ni][2] + b0, v3 = acc[mi][ni][3] + b1;
            if (layer == 0) {
                v0 = fmaxf(v0, 0.f); v1 = fmaxf(v1, 0.f);
                v2 = fmaxf(v2, 0.f); v3 = fmaxf(v3, 0.f);
                *(__half2*)(g_h1h + (size_t)row * 256 + col)       = __floats2half2_rn(v0, v1);
                *(__half2*)(g_h1h + (size_t)(row + 8) * 256 + col) = __floats2half2_rn(v2, v3);
            } else {
                *(float2*)(out_ext + (size_t)row * 256 + col)       = make_float2(v0, v1);
                *(float2*)(out_ext + (size_t)(row + 8) * 256 + col) = make_float2(v2, v3);
            }
        }
    }
}

// ---------------- launch ----------------
extern "C" void kernel_launch(void* const* d_in, const int* in_sizes, int n_in,
                              void* d_out, int out_size) {
    const float* x      = (const float*)d_in[0];
    const int*   edges  = (const int*)d_in[3];
    const int*   rel    = (const int*)d_in[4];
    const float* basis0 = (const float*)d_in[5];
    const float* comp0  = (const float*)d_in[6];
    const float* root0  = (const float*)d_in[7];
    const float* bias0  = (const float*)d_in[8];
    const float* basis1 = (const float*)d_in[9];
    const float* comp1  = (const float*)d_in[10];
    const float* root1  = (const float*)d_in[11];
    const float* bias1  = (const float*)d_in[12];
    float* out = (float*)d_out;

    const int* src = edges;
    const int* dst = edges + NEDGES;

    // one-time side objects (created on first call, before graph capture; no device mem)
    static cudaStream_t s2 = [] {
        cudaStream_t s;
        cudaStreamCreateWithFlags(&s, cudaStreamNonBlocking);
        return s;
    }();
    static cudaEvent_t evFork = [] {
        cudaEvent_t e;
        cudaEventCreateWithFlags(&e, cudaEventDisableTiming);
        return e;
    }();
    static cudaEvent_t evJoin = [] {
        cudaEvent_t e;
        cudaEventCreateWithFlags(&e, cudaEventDisableTiming);
        return e;
    }();
    static bool attr_set = [] {
        cudaFuncSetAttribute(gemm_fp16_kernel,
                             cudaFuncAttributeMaxDynamicSharedMemorySize, GEMM_SMEM);
        return true;
    }();
    (void)attr_set;

    // Fork: CSR chain on s2, operand prep on the main (captured) stream.
    cudaEventRecord(evFork, 0);
    cudaStreamWaitEvent(s2, evFork, 0);

    zero_counts_kernel<<<(NREL * NNODES + 255) / 256, 256, 0, s2>>>();
    hist_kernel<<<(NEDGES + 255) / 256, 256, 0, s2>>>(dst, rel);
    scan1_kernel<<<NNODES / 1024, 1024, 0, s2>>>();
    scan3_kernel<<<NNODES / 1024, 1024, 0, s2>>>();
    scatter_kernel<<<(NEDGES + 255) / 256, 256, 0, s2>>>(src, dst, rel);
    cudaEventRecord(evJoin, s2);

    prep_kernel<<<(NNODES * D + 255) / 256, 256>>>(x, basis0, root0, basis1, root1,
                                                   bias0, bias1, comp0, comp1);

    // Join before aggregation needs both chains.
    cudaStreamWaitEvent(0, evJoin, 0);

    // Layer 0: aggregate(x) -> S; [S|x] @ W0 + bias0, ReLU -> h1
    aggregate_kernel<<<NNODES / 16, 512>>>(0);
    gemm_fp16_kernel<<<NNODES / 64, 256, GEMM_SMEM>>>(nullptr, 0);

    // Layer 1: aggregate(h1) -> S; [S|h1] @ W1 + bias1 -> out
    aggregate_kernel<<<NNODES / 16, 512>>>(1);
    gemm_fp16_kernel<<<NNODES / 64, 256, GEMM_SMEM>>>(out, 1);
}